// round 1
// baseline (speedup 1.0000x reference)
#include <cuda_runtime.h>

// ---------------------------------------------------------------------------
// RGCN forward, fp32 baseline.
// Shapes: P=100000 papers, A=50000 authors, IN=128, H=256, OUT=349
// Edges: writes (A->P) 600k, cites (P->P) 1M, revw (P->A) 600k
// ---------------------------------------------------------------------------

#define P_N   100000
#define A_N   50000
#define IN_C  128
#define H_C   256
#define OUT_C 349

// Scratch (static device globals; no runtime allocation).
__device__ float g_hp  [(size_t)P_N * H_C];   // h_p after input projection
__device__ float g_outp[(size_t)P_N * H_C];   // layer0 paper accum -> relu -> hp1
__device__ float g_outa[(size_t)A_N * H_C];   // layer0 author accum -> relu -> ha1
__device__ float g_agg [(size_t)P_N * H_C];   // per-relation aggregation buffer
__device__ float g_cntW[P_N];
__device__ float g_cntC[P_N];
__device__ float g_cntR[A_N];

// ---------------------------------------------------------------------------
// Zero fill (float4)
// ---------------------------------------------------------------------------
__global__ void fill0_kernel(float4* __restrict__ p, int n4) {
    int i = blockIdx.x * blockDim.x + threadIdx.x;
    if (i < n4) p[i] = make_float4(0.f, 0.f, 0.f, 0.f);
}

// ---------------------------------------------------------------------------
// Edge degree count (float so the GEMM can consume directly)
// ---------------------------------------------------------------------------
__global__ void count_kernel(const int* __restrict__ dst, int E, float* __restrict__ cnt) {
    int i = blockIdx.x * blockDim.x + threadIdx.x;
    if (i < E) atomicAdd(&cnt[dst[i]], 1.0f);
}

// ---------------------------------------------------------------------------
// Scatter-add of 256-dim source rows into agg[dst]. 64 threads/edge, float4.
// ---------------------------------------------------------------------------
__global__ void scatter_add_kernel(const float* __restrict__ feat,
                                   const int* __restrict__ src,
                                   const int* __restrict__ dst,
                                   int E, float* __restrict__ agg) {
    long long gid = (long long)blockIdx.x * blockDim.x + threadIdx.x;
    long long total = (long long)E * 64;
    if (gid >= total) return;
    int e = (int)(gid >> 6);
    int c = ((int)gid & 63) * 4;
    int s = src[e];
    int d = dst[e];
    const float4 v = *(const float4*)&feat[(size_t)s * H_C + c];
    float* p = &agg[(size_t)d * H_C + c];
    atomicAdd(p + 0, v.x);
    atomicAdd(p + 1, v.y);
    atomicAdd(p + 2, v.z);
    atomicAdd(p + 3, v.w);
}

// ---------------------------------------------------------------------------
// Tiled fp32 GEMM: C[M,N] (+)= (rowscale(A)) @ B [+ bias] [relu]
//   BM=BN=64, BK=16, 16x16 threads, 4x4 micro-tile per thread.
//   SCALE: multiply row r of A by 1/max(cnt[r],1)  (fused mean)
//   ACC:   C += result (tile-disjoint, safe RMW)   else C = result + bias
//   RELU:  clamp at store
// ---------------------------------------------------------------------------
#define BM 64
#define BN 64
#define BK 16

template<bool ACC, bool RELU, bool SCALE>
__global__ void gemm_kernel(const float* __restrict__ A, const float* __restrict__ B,
                            const float* __restrict__ bias, const float* __restrict__ cnt,
                            float* __restrict__ C, int M, int N, int K) {
    __shared__ float As[BK][BM];   // transposed A tile
    __shared__ float Bs[BK][BN];

    const int tx = threadIdx.x, ty = threadIdx.y;       // 16 x 16
    const int t  = ty * 16 + tx;
    const int row0 = blockIdx.y * BM;
    const int col0 = blockIdx.x * BN;

    // Per-thread A-load rows are fixed across k-tiles: r = (t>>4) + 16*s
    float rscale[4];
    int   arow[4];
#pragma unroll
    for (int s = 0; s < 4; s++) {
        int r  = (t >> 4) + 16 * s;
        int gr = row0 + r;
        arow[s] = r;
        if (SCALE) {
            float cv = (gr < M) ? cnt[gr] : 1.f;
            rscale[s] = 1.0f / fmaxf(cv, 1.0f);
        } else {
            rscale[s] = 1.0f;
        }
    }

    float acc[4][4] = {};

    for (int k0 = 0; k0 < K; k0 += BK) {
        // A tile: 64 rows x 16 cols, store transposed
#pragma unroll
        for (int s = 0; s < 4; s++) {
            int r  = arow[s];
            int c  = t & 15;
            int gr = row0 + r;
            float v = 0.f;
            if (gr < M) v = A[(size_t)gr * K + (k0 + c)] * rscale[s];
            As[c][r] = v;
        }
        // B tile: 16 rows x 64 cols
#pragma unroll
        for (int s = 0; s < 4; s++) {
            int idx = t + s * 256;
            int r = idx >> 6, c = idx & 63;
            int gc = col0 + c;
            Bs[r][c] = (gc < N) ? B[(size_t)(k0 + r) * N + gc] : 0.f;
        }
        __syncthreads();

#pragma unroll
        for (int kk = 0; kk < BK; kk++) {
            float4 a4 = *(const float4*)&As[kk][ty * 4];
            float4 b4 = *(const float4*)&Bs[kk][tx * 4];
            float av[4] = {a4.x, a4.y, a4.z, a4.w};
            float bv[4] = {b4.x, b4.y, b4.z, b4.w};
#pragma unroll
            for (int i = 0; i < 4; i++)
#pragma unroll
                for (int j = 0; j < 4; j++)
                    acc[i][j] += av[i] * bv[j];
        }
        __syncthreads();
    }

    // Store
#pragma unroll
    for (int i = 0; i < 4; i++) {
        int gr = row0 + ty * 4 + i;
        if (gr >= M) continue;
#pragma unroll
        for (int j = 0; j < 4; j++) {
            int gc = col0 + tx * 4 + j;
            if (gc >= N) continue;
            size_t idx = (size_t)gr * N + gc;
            float v = acc[i][j];
            float out;
            if (ACC) out = C[idx] + v;
            else     out = v + bias[gc];
            if (RELU) out = fmaxf(out, 0.f);
            C[idx] = out;
        }
    }
}

// ---------------------------------------------------------------------------
// Row-wise log_softmax in place, one block (128 threads) per row.
// ---------------------------------------------------------------------------
__inline__ __device__ float warpMax(float v) {
#pragma unroll
    for (int o = 16; o; o >>= 1) v = fmaxf(v, __shfl_xor_sync(0xFFFFFFFFu, v, o));
    return v;
}
__inline__ __device__ float warpSum(float v) {
#pragma unroll
    for (int o = 16; o; o >>= 1) v += __shfl_xor_sync(0xFFFFFFFFu, v, o);
    return v;
}

__global__ void log_softmax_kernel(float* __restrict__ x, int N) {
    float* r = x + (size_t)blockIdx.x * N;
    int t = threadIdx.x;

    float m = -1e30f;
    for (int i = t; i < N; i += 128) m = fmaxf(m, r[i]);
    m = warpMax(m);
    __shared__ float shm[4];
    if ((t & 31) == 0) shm[t >> 5] = m;
    __syncthreads();
    m = fmaxf(fmaxf(shm[0], shm[1]), fmaxf(shm[2], shm[3]));

    float s = 0.f;
    for (int i = t; i < N; i += 128) s += expf(r[i] - m);
    s = warpSum(s);
    __shared__ float shs[4];
    if ((t & 31) == 0) shs[t >> 5] = s;
    __syncthreads();
    s = shs[0] + shs[1] + shs[2] + shs[3];

    float lse = m + logf(s);
    for (int i = t; i < N; i += 128) r[i] = r[i] - lse;
}

// ---------------------------------------------------------------------------
// Host-side helpers
// ---------------------------------------------------------------------------
static void run_gemm(int mode /*0: bias, 1: acc+scale, 2: acc+scale+relu*/,
                     const float* A, const float* B, const float* bias,
                     const float* cnt, float* C, int M, int N, int K) {
    dim3 grid((N + BN - 1) / BN, (M + BM - 1) / BM);
    dim3 block(16, 16);
    if (mode == 0)      gemm_kernel<false, false, false><<<grid, block>>>(A, B, bias, cnt, C, M, N, K);
    else if (mode == 1) gemm_kernel<true,  false, true ><<<grid, block>>>(A, B, bias, cnt, C, M, N, K);
    else                gemm_kernel<true,  true,  true ><<<grid, block>>>(A, B, bias, cnt, C, M, N, K);
}

static void run_fill0(float* p, size_t n) {
    int n4 = (int)(n / 4);
    fill0_kernel<<<(n4 + 255) / 256, 256>>>((float4*)p, n4);
}

static void run_scatter(const float* feat, const int* src, const int* dst, int E, float* agg) {
    long long total = (long long)E * 64;
    int blocks = (int)((total + 255) / 256);
    scatter_add_kernel<<<blocks, 256>>>(feat, src, dst, E, agg);
}

extern "C" void kernel_launch(void* const* d_in, const int* in_sizes, int n_in,
                              void* d_out, int out_size) {
    const float* x_paper          = (const float*)d_in[0];
    const float* emb_author       = (const float*)d_in[1];
    const float* lin_paper_w      = (const float*)d_in[2];
    const float* lin_paper_b      = (const float*)d_in[3];
    const float* c0_root_paper_w  = (const float*)d_in[4];
    const float* c0_root_paper_b  = (const float*)d_in[5];
    const float* c0_root_author_w = (const float*)d_in[6];
    const float* c0_root_author_b = (const float*)d_in[7];
    const float* c0_rel_writes_w  = (const float*)d_in[8];
    const float* c0_rel_cites_w   = (const float*)d_in[9];
    const float* c0_rel_revw_w    = (const float*)d_in[10];
    const float* c1_root_w        = (const float*)d_in[11];
    const float* c1_root_b        = (const float*)d_in[12];
    const float* c1_rel_writes_w  = (const float*)d_in[13];
    const float* c1_rel_cites_w   = (const float*)d_in[14];
    const int*   writes_src       = (const int*)d_in[15];
    const int*   writes_dst       = (const int*)d_in[16];
    const int*   cites_src        = (const int*)d_in[17];
    const int*   cites_dst        = (const int*)d_in[18];
    const int*   revw_src         = (const int*)d_in[19];
    const int*   revw_dst         = (const int*)d_in[20];

    const int E_W = in_sizes[15];
    const int E_C = in_sizes[17];

    float* out = (float*)d_out;

    float *hp, *outp, *outa, *agg, *cntW, *cntC, *cntR;
    cudaGetSymbolAddress((void**)&hp,   g_hp);
    cudaGetSymbolAddress((void**)&outp, g_outp);
    cudaGetSymbolAddress((void**)&outa, g_outa);
    cudaGetSymbolAddress((void**)&agg,  g_agg);
    cudaGetSymbolAddress((void**)&cntW, g_cntW);
    cudaGetSymbolAddress((void**)&cntC, g_cntC);
    cudaGetSymbolAddress((void**)&cntR, g_cntR);

    // Degree counts (reused by both layers)
    run_fill0(cntW, P_N);
    run_fill0(cntC, P_N);
    run_fill0(cntR, A_N);
    count_kernel<<<(E_W + 255) / 256, 256>>>(writes_dst, E_W, cntW);
    count_kernel<<<(E_C + 255) / 256, 256>>>(cites_dst,  E_C, cntC);
    count_kernel<<<(E_W + 255) / 256, 256>>>(revw_dst,   E_W, cntR);

    // Input projection: h_p = x_paper @ lin_paper_w + b
    run_gemm(0, x_paper, lin_paper_w, lin_paper_b, nullptr, hp, P_N, H_C, IN_C);

    // ---- Layer 0, paper side ----
    run_gemm(0, hp, c0_root_paper_w, c0_root_paper_b, nullptr, outp, P_N, H_C, H_C);

    run_fill0(agg, (size_t)P_N * H_C);
    run_scatter(emb_author, writes_src, writes_dst, E_W, agg);
    run_gemm(1, agg, c0_rel_writes_w, nullptr, cntW, outp, P_N, H_C, H_C);

    run_fill0(agg, (size_t)P_N * H_C);
    run_scatter(hp, cites_src, cites_dst, E_C, agg);
    run_gemm(2, agg, c0_rel_cites_w, nullptr, cntC, outp, P_N, H_C, H_C);  // + relu -> hp1

    // ---- Layer 0, author side ----
    run_gemm(0, emb_author, c0_root_author_w, c0_root_author_b, nullptr, outa, A_N, H_C, H_C);

    run_fill0(agg, (size_t)A_N * H_C);
    run_scatter(hp, revw_src, revw_dst, E_W, agg);
    run_gemm(2, agg, c0_rel_revw_w, nullptr, cntR, outa, A_N, H_C, H_C);   // + relu -> ha1

    // ---- Layer 1 (paper out only) ----
    run_gemm(0, outp, c1_root_w, c1_root_b, nullptr, out, P_N, OUT_C, H_C);

    run_fill0(agg, (size_t)P_N * H_C);
    run_scatter(outa, writes_src, writes_dst, E_W, agg);
    run_gemm(1, agg, c1_rel_writes_w, nullptr, cntW, out, P_N, OUT_C, H_C);

    run_fill0(agg, (size_t)P_N * H_C);
    run_scatter(outp, cites_src, cites_dst, E_C, agg);
    run_gemm(1, agg, c1_rel_cites_w, nullptr, cntC, out, P_N, OUT_C, H_C);

    // ---- log_softmax in place ----
    log_softmax_kernel<<<P_N, 128>>>(out, OUT_C);
}

// round 2
// speedup vs baseline: 1.4379x; 1.4379x over previous
#include <cuda_runtime.h>
#include <cuda_bf16.h>
#include <cstdint>

// ---------------------------------------------------------------------------
// RGCN forward. GEMMs on tensor pipe (bf16 HMMA, fp32 accumulate).
// P=100000, A=50000, IN=128, H=256, OUT=349
// ---------------------------------------------------------------------------

#define P_N   100000
#define A_N   50000
#define IN_C  128
#define H_C   256
#define OUT_C 349

__device__ float g_hp  [(size_t)P_N * H_C];
__device__ float g_outp[(size_t)P_N * H_C];
__device__ float g_outa[(size_t)A_N * H_C];
__device__ float g_agg [(size_t)P_N * H_C];
__device__ float g_cntW[P_N];
__device__ float g_cntC[P_N];
__device__ float g_cntR[A_N];

// ---------------------------------------------------------------------------
__global__ void fill0_kernel(float4* __restrict__ p, int n4) {
    int i = blockIdx.x * blockDim.x + threadIdx.x;
    if (i < n4) p[i] = make_float4(0.f, 0.f, 0.f, 0.f);
}

__global__ void count_kernel(const int* __restrict__ dst, int E, float* __restrict__ cnt) {
    int i = blockIdx.x * blockDim.x + threadIdx.x;
    if (i < E) atomicAdd(&cnt[dst[i]], 1.0f);
}

// Scatter-add of 256-dim source rows into agg[dst]. 64 threads/edge, float4.
__global__ void scatter_add_kernel(const float* __restrict__ feat,
                                   const int* __restrict__ src,
                                   const int* __restrict__ dst,
                                   int E, float* __restrict__ agg) {
    long long gid = (long long)blockIdx.x * blockDim.x + threadIdx.x;
    long long total = (long long)E * 64;
    if (gid >= total) return;
    int e = (int)(gid >> 6);
    int c = ((int)gid & 63) * 4;
    int s = src[e];
    int d = dst[e];
    const float4 v = *(const float4*)&feat[(size_t)s * H_C + c];
    float* p = &agg[(size_t)d * H_C + c];
    atomicAdd(p + 0, v.x);
    atomicAdd(p + 1, v.y);
    atomicAdd(p + 2, v.z);
    atomicAdd(p + 3, v.w);
}

// ---------------------------------------------------------------------------
// bf16 tensor-core GEMM: C[M,N] (+)= rowscale(A) @ B [+ bias] [relu]
// BM=128, BN=128, BK=32. 256 threads = 8 warps (2 in M x 4 in N).
// Warp tile 64x32 = 4 m16-frags x 4 n8-frags, mma.m16n8k16.bf16.
// A converted fp32->bf16 into smem (rowscale applied in fp32).
// ---------------------------------------------------------------------------
#define BM 128
#define BN 128
#define BK 32
#define PK 40   // smem row stride (bf16 elems), conflict-free for frag loads

template<bool ACC, bool RELU, bool SCALE>
__global__ __launch_bounds__(256, 2)
void gemm_bf16_kernel(const float* __restrict__ A, const float* __restrict__ B,
                      const float* __restrict__ bias, const float* __restrict__ cnt,
                      float* __restrict__ C, int M, int N, int K) {
    __shared__ __nv_bfloat16 As[BM][PK];   // row-major [m][k]
    __shared__ __nv_bfloat16 Bs[BN][PK];   // transposed [n][k]

    const int t    = threadIdx.x;
    const int lane = t & 31;
    const int w    = t >> 5;
    const int wm   = w & 1;        // 0..1  (64 rows each)
    const int wn   = w >> 1;       // 0..3  (32 cols each)
    const int g    = lane >> 2;    // 0..7
    const int tq   = lane & 3;     // 0..3
    const int row0 = blockIdx.y * BM;
    const int col0 = blockIdx.x * BN;

    float acc[4][4][4];
#pragma unroll
    for (int i = 0; i < 4; i++)
#pragma unroll
        for (int j = 0; j < 4; j++)
#pragma unroll
            for (int v = 0; v < 4; v++) acc[i][j][v] = 0.f;

    for (int k0 = 0; k0 < K; k0 += BK) {
        // ---- A tile: 128 rows x 32 k, fp32 -> bf16, rowscale fused ----
#pragma unroll
        for (int it = 0; it < 4; it++) {
            int idx = t + it * 256;        // 0..1023
            int r   = idx >> 3;            // 0..127
            int c4  = (idx & 7) * 4;       // 0..28
            int gr  = row0 + r;
            float4 v = make_float4(0.f, 0.f, 0.f, 0.f);
            float sc = 1.f;
            if (gr < M) {
                v = *(const float4*)&A[(size_t)gr * K + k0 + c4];
                if (SCALE) sc = 1.0f / fmaxf(cnt[gr], 1.0f);
            }
            *(__nv_bfloat162*)&As[r][c4]     = __floats2bfloat162_rn(v.x * sc, v.y * sc);
            *(__nv_bfloat162*)&As[r][c4 + 2] = __floats2bfloat162_rn(v.z * sc, v.w * sc);
        }
        // ---- B tile: 32 k x 128 n, transpose into Bs[n][k], guarded ----
#pragma unroll
        for (int it = 0; it < 4; it++) {
            int idx = t + it * 256;        // 0..1023
            int kr  = idx >> 5;            // 0..31
            int c4  = (idx & 31) * 4;      // 0..124
            const float* brow = &B[(size_t)(k0 + kr) * N];
#pragma unroll
            for (int e = 0; e < 4; e++) {
                int gc = col0 + c4 + e;
                float v = (gc < N) ? brow[gc] : 0.f;
                Bs[c4 + e][kr] = __float2bfloat16(v);
            }
        }
        __syncthreads();

        // ---- two k16 steps ----
#pragma unroll
        for (int ks = 0; ks < 2; ks++) {
            const int ko = ks * 16;
            uint32_t af[4][4];
            uint32_t bfr[4][2];
#pragma unroll
            for (int i = 0; i < 4; i++) {
                int r = wm * 64 + i * 16 + g;
                af[i][0] = *(const uint32_t*)&As[r][ko + tq * 2];
                af[i][1] = *(const uint32_t*)&As[r + 8][ko + tq * 2];
                af[i][2] = *(const uint32_t*)&As[r][ko + tq * 2 + 8];
                af[i][3] = *(const uint32_t*)&As[r + 8][ko + tq * 2 + 8];
            }
#pragma unroll
            for (int j = 0; j < 4; j++) {
                int n = wn * 32 + j * 8 + g;
                bfr[j][0] = *(const uint32_t*)&Bs[n][ko + tq * 2];
                bfr[j][1] = *(const uint32_t*)&Bs[n][ko + tq * 2 + 8];
            }
#pragma unroll
            for (int i = 0; i < 4; i++)
#pragma unroll
                for (int j = 0; j < 4; j++) {
                    asm volatile(
                        "mma.sync.aligned.m16n8k16.row.col.f32.bf16.bf16.f32 "
                        "{%0,%1,%2,%3}, {%4,%5,%6,%7}, {%8,%9}, {%0,%1,%2,%3};\n"
                        : "+f"(acc[i][j][0]), "+f"(acc[i][j][1]),
                          "+f"(acc[i][j][2]), "+f"(acc[i][j][3])
                        : "r"(af[i][0]), "r"(af[i][1]), "r"(af[i][2]), "r"(af[i][3]),
                          "r"(bfr[j][0]), "r"(bfr[j][1]));
                }
        }
        __syncthreads();
    }

    // ---- epilogue ----
#pragma unroll
    for (int i = 0; i < 4; i++) {
        int r0 = row0 + wm * 64 + i * 16 + g;
        int r1 = r0 + 8;
#pragma unroll
        for (int j = 0; j < 4; j++) {
            int c = col0 + wn * 32 + j * 8 + tq * 2;
#pragma unroll
            for (int h = 0; h < 2; h++) {
                int gc = c + h;
                if (gc >= N) continue;
                if (r0 < M) {
                    size_t idx = (size_t)r0 * N + gc;
                    float v = acc[i][j][h];
                    float o = ACC ? (C[idx] + v) : (v + bias[gc]);
                    if (RELU) o = fmaxf(o, 0.f);
                    C[idx] = o;
                }
                if (r1 < M) {
                    size_t idx = (size_t)r1 * N + gc;
                    float v = acc[i][j][2 + h];
                    float o = ACC ? (C[idx] + v) : (v + bias[gc]);
                    if (RELU) o = fmaxf(o, 0.f);
                    C[idx] = o;
                }
            }
        }
    }
}

// ---------------------------------------------------------------------------
// Row-wise log_softmax in place, one block (128 threads) per row.
// ---------------------------------------------------------------------------
__inline__ __device__ float warpMax(float v) {
#pragma unroll
    for (int o = 16; o; o >>= 1) v = fmaxf(v, __shfl_xor_sync(0xFFFFFFFFu, v, o));
    return v;
}
__inline__ __device__ float warpSum(float v) {
#pragma unroll
    for (int o = 16; o; o >>= 1) v += __shfl_xor_sync(0xFFFFFFFFu, v, o);
    return v;
}

__global__ void log_softmax_kernel(float* __restrict__ x, int N) {
    float* r = x + (size_t)blockIdx.x * N;
    int t = threadIdx.x;

    float m = -1e30f;
    for (int i = t; i < N; i += 128) m = fmaxf(m, r[i]);
    m = warpMax(m);
    __shared__ float shm[4];
    if ((t & 31) == 0) shm[t >> 5] = m;
    __syncthreads();
    m = fmaxf(fmaxf(shm[0], shm[1]), fmaxf(shm[2], shm[3]));

    float s = 0.f;
    for (int i = t; i < N; i += 128) s += expf(r[i] - m);
    s = warpSum(s);
    __shared__ float shs[4];
    if ((t & 31) == 0) shs[t >> 5] = s;
    __syncthreads();
    s = shs[0] + shs[1] + shs[2] + shs[3];

    float lse = m + logf(s);
    for (int i = t; i < N; i += 128) r[i] = r[i] - lse;
}

// ---------------------------------------------------------------------------
static void run_gemm(int mode /*0: bias, 1: acc+scale, 2: acc+scale+relu*/,
                     const float* A, const float* B, const float* bias,
                     const float* cnt, float* C, int M, int N, int K) {
    dim3 grid((N + BN - 1) / BN, (M + BM - 1) / BM);
    if (mode == 0)      gemm_bf16_kernel<false, false, false><<<grid, 256>>>(A, B, bias, cnt, C, M, N, K);
    else if (mode == 1) gemm_bf16_kernel<true,  false, true ><<<grid, 256>>>(A, B, bias, cnt, C, M, N, K);
    else                gemm_bf16_kernel<true,  true,  true ><<<grid, 256>>>(A, B, bias, cnt, C, M, N, K);
}

static void run_fill0(float* p, size_t n) {
    int n4 = (int)(n / 4);
    fill0_kernel<<<(n4 + 255) / 256, 256>>>((float4*)p, n4);
}

static void run_scatter(const float* feat, const int* src, const int* dst, int E, float* agg) {
    long long total = (long long)E * 64;
    int blocks = (int)((total + 255) / 256);
    scatter_add_kernel<<<blocks, 256>>>(feat, src, dst, E, agg);
}

extern "C" void kernel_launch(void* const* d_in, const int* in_sizes, int n_in,
                              void* d_out, int out_size) {
    const float* x_paper          = (const float*)d_in[0];
    const float* emb_author       = (const float*)d_in[1];
    const float* lin_paper_w      = (const float*)d_in[2];
    const float* lin_paper_b      = (const float*)d_in[3];
    const float* c0_root_paper_w  = (const float*)d_in[4];
    const float* c0_root_paper_b  = (const float*)d_in[5];
    const float* c0_root_author_w = (const float*)d_in[6];
    const float* c0_root_author_b = (const float*)d_in[7];
    const float* c0_rel_writes_w  = (const float*)d_in[8];
    const float* c0_rel_cites_w   = (const float*)d_in[9];
    const float* c0_rel_revw_w    = (const float*)d_in[10];
    const float* c1_root_w        = (const float*)d_in[11];
    const float* c1_root_b        = (const float*)d_in[12];
    const float* c1_rel_writes_w  = (const float*)d_in[13];
    const float* c1_rel_cites_w   = (const float*)d_in[14];
    const int*   writes_src       = (const int*)d_in[15];
    const int*   writes_dst       = (const int*)d_in[16];
    const int*   cites_src        = (const int*)d_in[17];
    const int*   cites_dst        = (const int*)d_in[18];
    const int*   revw_src         = (const int*)d_in[19];
    const int*   revw_dst         = (const int*)d_in[20];

    const int E_W = in_sizes[15];
    const int E_C = in_sizes[17];

    float* out = (float*)d_out;

    float *hp, *outp, *outa, *agg, *cntW, *cntC, *cntR;
    cudaGetSymbolAddress((void**)&hp,   g_hp);
    cudaGetSymbolAddress((void**)&outp, g_outp);
    cudaGetSymbolAddress((void**)&outa, g_outa);
    cudaGetSymbolAddress((void**)&agg,  g_agg);
    cudaGetSymbolAddress((void**)&cntW, g_cntW);
    cudaGetSymbolAddress((void**)&cntC, g_cntC);
    cudaGetSymbolAddress((void**)&cntR, g_cntR);

    // Degree counts (reused by both layers)
    run_fill0(cntW, P_N);
    run_fill0(cntC, P_N);
    run_fill0(cntR, A_N);
    count_kernel<<<(E_W + 255) / 256, 256>>>(writes_dst, E_W, cntW);
    count_kernel<<<(E_C + 255) / 256, 256>>>(cites_dst,  E_C, cntC);
    count_kernel<<<(E_W + 255) / 256, 256>>>(revw_dst,   E_W, cntR);

    // Input projection: h_p = x_paper @ lin_paper_w + b
    run_gemm(0, x_paper, lin_paper_w, lin_paper_b, nullptr, hp, P_N, H_C, IN_C);

    // ---- Layer 0, paper side ----
    run_gemm(0, hp, c0_root_paper_w, c0_root_paper_b, nullptr, outp, P_N, H_C, H_C);

    run_fill0(agg, (size_t)P_N * H_C);
    run_scatter(emb_author, writes_src, writes_dst, E_W, agg);
    run_gemm(1, agg, c0_rel_writes_w, nullptr, cntW, outp, P_N, H_C, H_C);

    run_fill0(agg, (size_t)P_N * H_C);
    run_scatter(hp, cites_src, cites_dst, E_C, agg);
    run_gemm(2, agg, c0_rel_cites_w, nullptr, cntC, outp, P_N, H_C, H_C);  // + relu

    // ---- Layer 0, author side ----
    run_gemm(0, emb_author, c0_root_author_w, c0_root_author_b, nullptr, outa, A_N, H_C, H_C);

    run_fill0(agg, (size_t)A_N * H_C);
    run_scatter(hp, revw_src, revw_dst, E_W, agg);
    run_gemm(2, agg, c0_rel_revw_w, nullptr, cntR, outa, A_N, H_C, H_C);   // + relu

    // ---- Layer 1 (paper out only) ----
    run_gemm(0, outp, c1_root_w, c1_root_b, nullptr, out, P_N, OUT_C, H_C);

    run_fill0(agg, (size_t)P_N * H_C);
    run_scatter(outa, writes_src, writes_dst, E_W, agg);
    run_gemm(1, agg, c1_rel_writes_w, nullptr, cntW, out, P_N, OUT_C, H_C);

    run_fill0(agg, (size_t)P_N * H_C);
    run_scatter(outp, cites_src, cites_dst, E_C, agg);
    run_gemm(1, agg, c1_rel_cites_w, nullptr, cntC, out, P_N, OUT_C, H_C);

    // ---- log_softmax in place ----
    log_softmax_kernel<<<P_N, 128>>>(out, OUT_C);
}

// round 3
// speedup vs baseline: 2.1107x; 1.4679x over previous
#include <cuda_runtime.h>
#include <cuda_bf16.h>
#include <cstdint>

// ---------------------------------------------------------------------------
// RGCN forward. bf16 HMMA GEMMs (K-fused, multi-segment), v4 atomic scatter.
// P=100000, A=50000, IN=128, H=256, OUT=349
// ---------------------------------------------------------------------------

#define P_N   100000
#define A_N   50000
#define IN_C  128
#define H_C   256
#define OUT_C 349

__device__ float g_hp  [(size_t)P_N * H_C];
__device__ float g_outp[(size_t)P_N * H_C];
__device__ float g_outa[(size_t)A_N * H_C];
__device__ float g_aggA[(size_t)P_N * H_C];
__device__ float g_aggB[(size_t)P_N * H_C];
__device__ float g_cntW[P_N];
__device__ float g_cntC[P_N];
__device__ float g_cntR[A_N];

// ---------------------------------------------------------------------------
__global__ void fill0_kernel(float4* __restrict__ p, int n4) {
    int i = blockIdx.x * blockDim.x + threadIdx.x;
    if (i < n4) p[i] = make_float4(0.f, 0.f, 0.f, 0.f);
}

__global__ void count_kernel(const int* __restrict__ dst, int E, float* __restrict__ cnt) {
    int i = blockIdx.x * blockDim.x + threadIdx.x;
    if (i < E) atomicAdd(&cnt[dst[i]], 1.0f);
}

// ---------------------------------------------------------------------------
// Scatter-add of 256-dim rows into agg[dst]. 64 threads/edge, one
// red.global.add.v4.f32 per thread (16B RMW instead of 4x 4B).
// ---------------------------------------------------------------------------
__global__ void scatter_add_kernel(const float* __restrict__ feat,
                                   const int* __restrict__ src,
                                   const int* __restrict__ dst,
                                   int E, float* __restrict__ agg) {
    long long gid = (long long)blockIdx.x * blockDim.x + threadIdx.x;
    long long total = (long long)E * 64;
    if (gid >= total) return;
    int e = (int)(gid >> 6);
    int c = ((int)gid & 63) * 4;
    int s = src[e];
    int d = dst[e];
    const float4 v = *(const float4*)&feat[(size_t)s * H_C + c];
    float* p = &agg[(size_t)d * H_C + c];
    asm volatile("red.global.add.v4.f32 [%0], {%1, %2, %3, %4};"
                 :: "l"(p), "f"(v.x), "f"(v.y), "f"(v.z), "f"(v.w)
                 : "memory");
}

// ---------------------------------------------------------------------------
// Fused multi-segment bf16 GEMM:
//   C[M,N] = sum_s rowscale_s(A_s[M,K_s]) @ B_s[K_s,N]  + bias  [relu]
// BM=BN=128, BK=32, 256 threads = 8 warps (2M x 4N), mma.m16n8k16.bf16.
// ---------------------------------------------------------------------------
#define BM 128
#define BN 128
#define BK 32
#define PK 40   // smem row stride in bf16 elems (20 words): frag loads conflict-free

struct GemmParams {
    const float* A[3];
    const float* B[3];
    const float* cnt[3];   // nullptr -> no row scaling for that segment
    int          K[3];
    int          nseg;
    const float* bias;
    float*       C;
    int          M, N;
};

template<bool RELU>
__global__ __launch_bounds__(256, 2)
void gemm_fused_kernel(GemmParams p) {
    __shared__ __nv_bfloat16 As[BM][PK];   // [m][k]
    __shared__ __nv_bfloat16 Bs[BN][PK];   // [n][k] (transposed)

    const int t    = threadIdx.x;
    const int lane = t & 31;
    const int w    = t >> 5;
    const int wm   = w & 1;
    const int wn   = w >> 1;
    const int g    = lane >> 2;
    const int tq   = lane & 3;
    const int row0 = blockIdx.y * BM;
    const int col0 = blockIdx.x * BN;
    const int M = p.M, N = p.N;

    float acc[4][4][4];
#pragma unroll
    for (int i = 0; i < 4; i++)
#pragma unroll
        for (int j = 0; j < 4; j++)
#pragma unroll
            for (int v = 0; v < 4; v++) acc[i][j][v] = 0.f;

    for (int s = 0; s < p.nseg; s++) {
        const float* __restrict__ A   = p.A[s];
        const float* __restrict__ B   = p.B[s];
        const float* __restrict__ cnt = p.cnt[s];
        const int K = p.K[s];

        // per-thread row scale for the A-load rows of this segment
        float rscale = 1.f;
        {
            int r  = t >> 3;           // A-load row handled by this thread (it stride 32)
            (void)r;
        }

        for (int k0 = 0; k0 < K; k0 += BK) {
            // ---- A tile: 128 rows x 32 k, fp32 -> bf16, rowscale fused ----
#pragma unroll
            for (int it = 0; it < 4; it++) {
                int idx = t + it * 256;        // 0..1023
                int r   = idx >> 3;            // 0..127
                int c4  = (idx & 7) * 4;       // 0,4,..,28
                int gr  = row0 + r;
                float4 v = make_float4(0.f, 0.f, 0.f, 0.f);
                float sc = 1.f;
                if (gr < M) {
                    v = *(const float4*)&A[(size_t)gr * K + k0 + c4];
                    if (cnt) sc = 1.0f / fmaxf(cnt[gr], 1.0f);
                }
                *(__nv_bfloat162*)&As[r][c4]     = __floats2bfloat162_rn(v.x * sc, v.y * sc);
                *(__nv_bfloat162*)&As[r][c4 + 2] = __floats2bfloat162_rn(v.z * sc, v.w * sc);
            }
            // ---- B tile: transpose [32k x 128n] -> Bs[n][k], bf16x2 along k ----
#pragma unroll
            for (int it = 0; it < 8; it++) {
                int idx = t + it * 256;        // 0..2047
                int n   = idx & 127;
                int kp  = idx >> 7;            // 0..15 (k pair)
                int gc  = col0 + n;
                float v0 = 0.f, v1 = 0.f;
                if (gc < N) {
                    v0 = B[(size_t)(k0 + 2 * kp)     * N + gc];
                    v1 = B[(size_t)(k0 + 2 * kp + 1) * N + gc];
                }
                *(__nv_bfloat162*)&Bs[n][2 * kp] = __floats2bfloat162_rn(v0, v1);
            }
            __syncthreads();

            // ---- two k16 steps ----
#pragma unroll
            for (int ks = 0; ks < 2; ks++) {
                const int ko = ks * 16;
                uint32_t af[4][4];
                uint32_t bfr[4][2];
#pragma unroll
                for (int i = 0; i < 4; i++) {
                    int r = wm * 64 + i * 16 + g;
                    af[i][0] = *(const uint32_t*)&As[r][ko + tq * 2];
                    af[i][1] = *(const uint32_t*)&As[r + 8][ko + tq * 2];
                    af[i][2] = *(const uint32_t*)&As[r][ko + tq * 2 + 8];
                    af[i][3] = *(const uint32_t*)&As[r + 8][ko + tq * 2 + 8];
                }
#pragma unroll
                for (int j = 0; j < 4; j++) {
                    int n = wn * 32 + j * 8 + g;
                    bfr[j][0] = *(const uint32_t*)&Bs[n][ko + tq * 2];
                    bfr[j][1] = *(const uint32_t*)&Bs[n][ko + tq * 2 + 8];
                }
#pragma unroll
                for (int i = 0; i < 4; i++)
#pragma unroll
                    for (int j = 0; j < 4; j++) {
                        asm volatile(
                            "mma.sync.aligned.m16n8k16.row.col.f32.bf16.bf16.f32 "
                            "{%0,%1,%2,%3}, {%4,%5,%6,%7}, {%8,%9}, {%0,%1,%2,%3};\n"
                            : "+f"(acc[i][j][0]), "+f"(acc[i][j][1]),
                              "+f"(acc[i][j][2]), "+f"(acc[i][j][3])
                            : "r"(af[i][0]), "r"(af[i][1]), "r"(af[i][2]), "r"(af[i][3]),
                              "r"(bfr[j][0]), "r"(bfr[j][1]));
                    }
            }
            __syncthreads();
        }
    }

    // ---- epilogue: + bias, optional relu ----
#pragma unroll
    for (int i = 0; i < 4; i++) {
        int r0 = row0 + wm * 64 + i * 16 + g;
        int r1 = r0 + 8;
#pragma unroll
        for (int j = 0; j < 4; j++) {
            int c = col0 + wn * 32 + j * 8 + tq * 2;
#pragma unroll
            for (int h = 0; h < 2; h++) {
                int gc = c + h;
                if (gc >= N) continue;
                float b = p.bias[gc];
                if (r0 < M) {
                    float o = acc[i][j][h] + b;
                    if (RELU) o = fmaxf(o, 0.f);
                    p.C[(size_t)r0 * N + gc] = o;
                }
                if (r1 < M) {
                    float o = acc[i][j][2 + h] + b;
                    if (RELU) o = fmaxf(o, 0.f);
                    p.C[(size_t)r1 * N + gc] = o;
                }
            }
        }
    }
}

// ---------------------------------------------------------------------------
// Row-wise log_softmax in place, one block (128 threads) per row.
// ---------------------------------------------------------------------------
__inline__ __device__ float warpMax(float v) {
#pragma unroll
    for (int o = 16; o; o >>= 1) v = fmaxf(v, __shfl_xor_sync(0xFFFFFFFFu, v, o));
    return v;
}
__inline__ __device__ float warpSum(float v) {
#pragma unroll
    for (int o = 16; o; o >>= 1) v += __shfl_xor_sync(0xFFFFFFFFu, v, o);
    return v;
}

__global__ void log_softmax_kernel(float* __restrict__ x, int N) {
    float* r = x + (size_t)blockIdx.x * N;
    int t = threadIdx.x;

    float m = -1e30f;
    for (int i = t; i < N; i += 128) m = fmaxf(m, r[i]);
    m = warpMax(m);
    __shared__ float shm[4];
    if ((t & 31) == 0) shm[t >> 5] = m;
    __syncthreads();
    m = fmaxf(fmaxf(shm[0], shm[1]), fmaxf(shm[2], shm[3]));

    float s = 0.f;
    for (int i = t; i < N; i += 128) s += expf(r[i] - m);
    s = warpSum(s);
    __shared__ float shs[4];
    if ((t & 31) == 0) shs[t >> 5] = s;
    __syncthreads();
    s = shs[0] + shs[1] + shs[2] + shs[3];

    float lse = m + logf(s);
    for (int i = t; i < N; i += 128) r[i] = r[i] - lse;
}

// ---------------------------------------------------------------------------
static void run_fill0(float* p, size_t n) {
    int n4 = (int)(n / 4);
    fill0_kernel<<<(n4 + 255) / 256, 256>>>((float4*)p, n4);
}

static void run_scatter(const float* feat, const int* src, const int* dst, int E, float* agg) {
    long long total = (long long)E * 64;
    int blocks = (int)((total + 255) / 256);
    scatter_add_kernel<<<blocks, 256>>>(feat, src, dst, E, agg);
}

static void run_gemm_fused(bool relu, const GemmParams& p) {
    dim3 grid((p.N + BN - 1) / BN, (p.M + BM - 1) / BM);
    if (relu) gemm_fused_kernel<true ><<<grid, 256>>>(p);
    else      gemm_fused_kernel<false><<<grid, 256>>>(p);
}

extern "C" void kernel_launch(void* const* d_in, const int* in_sizes, int n_in,
                              void* d_out, int out_size) {
    const float* x_paper          = (const float*)d_in[0];
    const float* emb_author       = (const float*)d_in[1];
    const float* lin_paper_w      = (const float*)d_in[2];
    const float* lin_paper_b      = (const float*)d_in[3];
    const float* c0_root_paper_w  = (const float*)d_in[4];
    const float* c0_root_paper_b  = (const float*)d_in[5];
    const float* c0_root_author_w = (const float*)d_in[6];
    const float* c0_root_author_b = (const float*)d_in[7];
    const float* c0_rel_writes_w  = (const float*)d_in[8];
    const float* c0_rel_cites_w   = (const float*)d_in[9];
    const float* c0_rel_revw_w    = (const float*)d_in[10];
    const float* c1_root_w        = (const float*)d_in[11];
    const float* c1_root_b        = (const float*)d_in[12];
    const float* c1_rel_writes_w  = (const float*)d_in[13];
    const float* c1_rel_cites_w   = (const float*)d_in[14];
    const int*   writes_src       = (const int*)d_in[15];
    const int*   writes_dst       = (const int*)d_in[16];
    const int*   cites_src        = (const int*)d_in[17];
    const int*   cites_dst        = (const int*)d_in[18];
    const int*   revw_src         = (const int*)d_in[19];
    const int*   revw_dst         = (const int*)d_in[20];

    const int E_W = in_sizes[15];
    const int E_C = in_sizes[17];

    float* out = (float*)d_out;

    float *hp, *outp, *outa, *aggA, *aggB, *cntW, *cntC, *cntR;
    cudaGetSymbolAddress((void**)&hp,   g_hp);
    cudaGetSymbolAddress((void**)&outp, g_outp);
    cudaGetSymbolAddress((void**)&outa, g_outa);
    cudaGetSymbolAddress((void**)&aggA, g_aggA);
    cudaGetSymbolAddress((void**)&aggB, g_aggB);
    cudaGetSymbolAddress((void**)&cntW, g_cntW);
    cudaGetSymbolAddress((void**)&cntC, g_cntC);
    cudaGetSymbolAddress((void**)&cntR, g_cntR);

    // Degree counts (reused by both layers)
    run_fill0(cntW, P_N);
    run_fill0(cntC, P_N);
    run_fill0(cntR, A_N);
    count_kernel<<<(E_W + 255) / 256, 256>>>(writes_dst, E_W, cntW);
    count_kernel<<<(E_C + 255) / 256, 256>>>(cites_dst,  E_C, cntC);
    count_kernel<<<(E_W + 255) / 256, 256>>>(revw_dst,   E_W, cntR);

    // 1) Input projection: h_p = x_paper @ lin_paper_w + b
    {
        GemmParams p = {};
        p.A[0] = x_paper; p.B[0] = lin_paper_w; p.cnt[0] = nullptr; p.K[0] = IN_C;
        p.nseg = 1; p.bias = lin_paper_b; p.C = hp; p.M = P_N; p.N = H_C;
        run_gemm_fused(false, p);
    }

    // 2) Layer-0 aggregations for paper dst
    run_fill0(aggA, (size_t)P_N * H_C);
    run_fill0(aggB, (size_t)P_N * H_C);
    run_scatter(emb_author, writes_src, writes_dst, E_W, aggA);
    run_scatter(hp,         cites_src,  cites_dst,  E_C, aggB);

    // 3) out_p = relu(hp@Wroot + mean(aggA)@Ww + mean(aggB)@Wc + b)
    {
        GemmParams p = {};
        p.A[0] = hp;   p.B[0] = c0_root_paper_w; p.cnt[0] = nullptr; p.K[0] = H_C;
        p.A[1] = aggA; p.B[1] = c0_rel_writes_w; p.cnt[1] = cntW;    p.K[1] = H_C;
        p.A[2] = aggB; p.B[2] = c0_rel_cites_w;  p.cnt[2] = cntC;    p.K[2] = H_C;
        p.nseg = 3; p.bias = c0_root_paper_b; p.C = outp; p.M = P_N; p.N = H_C;
        run_gemm_fused(true, p);
    }

    // 4) Author side: agg revw(hp) then fused 2-segment GEMM + relu
    run_fill0(aggA, (size_t)A_N * H_C);
    run_scatter(hp, revw_src, revw_dst, E_W, aggA);
    {
        GemmParams p = {};
        p.A[0] = emb_author; p.B[0] = c0_root_author_w; p.cnt[0] = nullptr; p.K[0] = H_C;
        p.A[1] = aggA;       p.B[1] = c0_rel_revw_w;    p.cnt[1] = cntR;    p.K[1] = H_C;
        p.nseg = 2; p.bias = c0_root_author_b; p.C = outa; p.M = A_N; p.N = H_C;
        run_gemm_fused(true, p);
    }

    // 5) Layer-1 aggregations
    run_fill0(aggA, (size_t)P_N * H_C);
    run_fill0(aggB, (size_t)P_N * H_C);
    run_scatter(outa, writes_src, writes_dst, E_W, aggA);
    run_scatter(outp, cites_src,  cites_dst,  E_C, aggB);

    // 6) out = outp@W1root + mean(aggA)@W1w + mean(aggB)@W1c + b
    {
        GemmParams p = {};
        p.A[0] = outp; p.B[0] = c1_root_w;       p.cnt[0] = nullptr; p.K[0] = H_C;
        p.A[1] = aggA; p.B[1] = c1_rel_writes_w; p.cnt[1] = cntW;    p.K[1] = H_C;
        p.A[2] = aggB; p.B[2] = c1_rel_cites_w;  p.cnt[2] = cntC;    p.K[2] = H_C;
        p.nseg = 3; p.bias = c1_root_b; p.C = out; p.M = P_N; p.N = OUT_C;
        run_gemm_fused(false, p);
    }

    // 7) log_softmax in place
    log_softmax_kernel<<<P_N, 128>>>(out, OUT_C);
}

// round 4
// speedup vs baseline: 3.4046x; 1.6130x over previous
#include <cuda_runtime.h>
#include <cuda_bf16.h>
#include <cstdint>

// ---------------------------------------------------------------------------
// RGCN forward. CSR gather-mean aggregation (bf16 features), bf16 HMMA GEMMs.
// P=100000, A=50000, IN=128, H=256, OUT=349
// ---------------------------------------------------------------------------

#define P_N   100000
#define A_N   50000
#define IN_C  128
#define H_C   256
#define OUT_C 349
#define EW_MAX 600000
#define EC_MAX 1000000

// bf16 feature buffers
__device__ __nv_bfloat16 g_hp  [(size_t)P_N * H_C];
__device__ __nv_bfloat16 g_outp[(size_t)P_N * H_C];
__device__ __nv_bfloat16 g_outa[(size_t)A_N * H_C];
__device__ __nv_bfloat16 g_aggA[(size_t)P_N * H_C];
__device__ __nv_bfloat16 g_aggB[(size_t)P_N * H_C];
__device__ __nv_bfloat16 g_emba[(size_t)A_N * H_C];

// CSR scratch
__device__ int g_cntW[P_N], g_cntC[P_N], g_cntR[A_N];
__device__ int g_rpW[P_N + 1], g_rpC[P_N + 1], g_rpR[A_N + 1];
__device__ int g_nxW[P_N], g_nxC[P_N], g_nxR[A_N];
__device__ int g_csW[EW_MAX], g_csC[EC_MAX], g_csR[EW_MAX];
__device__ int g_bsum[1024];

// ---------------------------------------------------------------------------
__global__ void fill0_kernel(float4* __restrict__ p, int n4) {
    int i = blockIdx.x * blockDim.x + threadIdx.x;
    if (i < n4) p[i] = make_float4(0.f, 0.f, 0.f, 0.f);
}

__global__ void count_int_kernel(const int* __restrict__ dst, int E, int* __restrict__ cnt) {
    int i = blockIdx.x * blockDim.x + threadIdx.x;
    if (i < E) atomicAdd(&cnt[dst[i]], 1);
}

// ---------------------------------------------------------------------------
// 3-phase exclusive scan (counts -> rowptr, and a mutable copy nextp)
// ---------------------------------------------------------------------------
#define SCB 1024

__global__ void scan1_kernel(const int* __restrict__ cnt, int n, int* __restrict__ bsum) {
    __shared__ int sh[SCB];
    int tid = threadIdx.x;
    int i = blockIdx.x * SCB + tid;
    sh[tid] = (i < n) ? cnt[i] : 0;
    __syncthreads();
    for (int off = SCB / 2; off; off >>= 1) {
        if (tid < off) sh[tid] += sh[tid + off];
        __syncthreads();
    }
    if (!tid) bsum[blockIdx.x] = sh[0];
}

__global__ void scan2_kernel(int* __restrict__ bsum, int nb) {
    __shared__ int sh[SCB];
    int tid = threadIdx.x;
    int v = (tid < nb) ? bsum[tid] : 0;
    sh[tid] = v;
    __syncthreads();
    for (int off = 1; off < SCB; off <<= 1) {
        int a = (tid >= off) ? sh[tid - off] : 0;
        __syncthreads();
        sh[tid] += a;
        __syncthreads();
    }
    if (tid < nb) bsum[tid] = sh[tid] - v;   // exclusive
}

__global__ void scan3_kernel(const int* __restrict__ cnt, int n, const int* __restrict__ bsum,
                             int* __restrict__ rowptr, int* __restrict__ nextp) {
    __shared__ int sh[SCB];
    int tid = threadIdx.x;
    int i = blockIdx.x * SCB + tid;
    int v = (i < n) ? cnt[i] : 0;
    sh[tid] = v;
    __syncthreads();
    for (int off = 1; off < SCB; off <<= 1) {
        int a = (tid >= off) ? sh[tid - off] : 0;
        __syncthreads();
        sh[tid] += a;
        __syncthreads();
    }
    int excl = sh[tid] - v + bsum[blockIdx.x];
    if (i < n) { rowptr[i] = excl; nextp[i] = excl; }
    if (i == n - 1) rowptr[n] = excl + v;
}

__global__ void build_csr_kernel(const int* __restrict__ src, const int* __restrict__ dst,
                                 int E, int* __restrict__ nextp, int* __restrict__ csr_src) {
    int i = blockIdx.x * blockDim.x + threadIdx.x;
    if (i < E) {
        int p = atomicAdd(&nextp[dst[i]], 1);
        csr_src[p] = src[i];
    }
}

// ---------------------------------------------------------------------------
// fp32 -> bf16 convert (vector of 4)
// ---------------------------------------------------------------------------
__global__ void f2b_kernel(const float4* __restrict__ in, uint2* __restrict__ out, int n4) {
    int i = blockIdx.x * blockDim.x + threadIdx.x;
    if (i >= n4) return;
    float4 v = in[i];
    __nv_bfloat162 a = __floats2bfloat162_rn(v.x, v.y);
    __nv_bfloat162 b = __floats2bfloat162_rn(v.z, v.w);
    uint2 o;
    o.x = *(uint32_t*)&a;
    o.y = *(uint32_t*)&b;
    out[i] = o;
}

// ---------------------------------------------------------------------------
// Gather-mean: agg[d] = mean over neighbors src of feat[src]  (bf16 in/out,
// fp32 accumulation). 64 threads per dst row (4 rows per 256-thread block).
// ---------------------------------------------------------------------------
__global__ void gather_mean_kernel(const __nv_bfloat16* __restrict__ feat,
                                   const int* __restrict__ rowptr,
                                   const int* __restrict__ csr_src,
                                   int num_dst,
                                   __nv_bfloat16* __restrict__ agg) {
    int group = blockIdx.x * 4 + (threadIdx.x >> 6);
    int lane  = threadIdx.x & 63;
    if (group >= num_dst) return;
    int beg = rowptr[group], end = rowptr[group + 1];
    int c4 = lane * 4;

    float s0 = 0.f, s1 = 0.f, s2 = 0.f, s3 = 0.f;
    int i = beg;
    for (; i + 1 < end; i += 2) {
        int sa = csr_src[i];
        int sb = csr_src[i + 1];
        uint2 ua = *(const uint2*)&feat[(size_t)sa * H_C + c4];
        uint2 ub = *(const uint2*)&feat[(size_t)sb * H_C + c4];
        float2 a0 = __bfloat1622float2(*(__nv_bfloat162*)&ua.x);
        float2 a1 = __bfloat1622float2(*(__nv_bfloat162*)&ua.y);
        float2 b0 = __bfloat1622float2(*(__nv_bfloat162*)&ub.x);
        float2 b1 = __bfloat1622float2(*(__nv_bfloat162*)&ub.y);
        s0 += a0.x + b0.x; s1 += a0.y + b0.y;
        s2 += a1.x + b1.x; s3 += a1.y + b1.y;
    }
    if (i < end) {
        int sa = csr_src[i];
        uint2 ua = *(const uint2*)&feat[(size_t)sa * H_C + c4];
        float2 a0 = __bfloat1622float2(*(__nv_bfloat162*)&ua.x);
        float2 a1 = __bfloat1622float2(*(__nv_bfloat162*)&ua.y);
        s0 += a0.x; s1 += a0.y; s2 += a1.x; s3 += a1.y;
    }
    float inv = (end > beg) ? 1.0f / (float)(end - beg) : 0.f;
    __nv_bfloat162 o0 = __floats2bfloat162_rn(s0 * inv, s1 * inv);
    __nv_bfloat162 o1 = __floats2bfloat162_rn(s2 * inv, s3 * inv);
    uint2 o;
    o.x = *(uint32_t*)&o0;
    o.y = *(uint32_t*)&o1;
    *(uint2*)&agg[(size_t)group * H_C + c4] = o;
}

// ---------------------------------------------------------------------------
// Fused multi-segment bf16 GEMM:
//   C[M,N] = sum_s A_s[M,K_s] @ B_s[K_s,N] + bias  [relu]
// A segments: bf16 or fp32 (converted on load). B: fp32 weights.
// BM=BN=128, BK=32, 256 threads = 8 warps (2M x 4N), mma.m16n8k16.bf16.
// ---------------------------------------------------------------------------
#define BM 128
#define BN 128
#define BK 32
#define PK 40   // smem row stride in bf16 elems

struct GemmParams {
    const void*  A[3];
    const float* B[3];
    int          K[3];
    int          abf16[3];
    int          nseg;
    const float* bias;
    void*        C;
    int          M, N;
};

template<bool RELU, bool OUTBF16>
__global__ __launch_bounds__(256, 2)
void gemm_fused_kernel(GemmParams p) {
    __shared__ __nv_bfloat16 As[BM][PK];   // [m][k]
    __shared__ __nv_bfloat16 Bs[BN][PK];   // [n][k] (transposed)

    const int t    = threadIdx.x;
    const int lane = t & 31;
    const int w    = t >> 5;
    const int wm   = w & 1;
    const int wn   = w >> 1;
    const int g    = lane >> 2;
    const int tq   = lane & 3;
    const int row0 = blockIdx.y * BM;
    const int col0 = blockIdx.x * BN;
    const int M = p.M, N = p.N;

    float acc[4][4][4];
#pragma unroll
    for (int i = 0; i < 4; i++)
#pragma unroll
        for (int j = 0; j < 4; j++)
#pragma unroll
            for (int v = 0; v < 4; v++) acc[i][j][v] = 0.f;

    for (int s = 0; s < p.nseg; s++) {
        const float* __restrict__ B = p.B[s];
        const int K = p.K[s];
        const bool abf = (p.abf16[s] != 0);
        const __nv_bfloat16* __restrict__ Ab = (const __nv_bfloat16*)p.A[s];
        const float* __restrict__ Af = (const float*)p.A[s];

        for (int k0 = 0; k0 < K; k0 += BK) {
            // ---- A tile: 128 rows x 32 k ----
#pragma unroll
            for (int it = 0; it < 4; it++) {
                int idx = t + it * 256;        // 0..1023
                int r   = idx >> 3;            // 0..127
                int c4  = (idx & 7) * 4;       // 0,4,..,28
                int gr  = row0 + r;
                if (abf) {
                    uint2 v = make_uint2(0u, 0u);
                    if (gr < M) v = *(const uint2*)&Ab[(size_t)gr * K + k0 + c4];
                    *(uint2*)&As[r][c4] = v;
                } else {
                    float4 v = make_float4(0.f, 0.f, 0.f, 0.f);
                    if (gr < M) v = *(const float4*)&Af[(size_t)gr * K + k0 + c4];
                    *(__nv_bfloat162*)&As[r][c4]     = __floats2bfloat162_rn(v.x, v.y);
                    *(__nv_bfloat162*)&As[r][c4 + 2] = __floats2bfloat162_rn(v.z, v.w);
                }
            }
            // ---- B tile: transpose [32k x 128n] -> Bs[n][k], bf16x2 along k ----
#pragma unroll
            for (int it = 0; it < 8; it++) {
                int idx = t + it * 256;        // 0..2047
                int n   = idx & 127;
                int kp  = idx >> 7;            // 0..15 (k pair)
                int gc  = col0 + n;
                float v0 = 0.f, v1 = 0.f;
                if (gc < N) {
                    v0 = B[(size_t)(k0 + 2 * kp)     * N + gc];
                    v1 = B[(size_t)(k0 + 2 * kp + 1) * N + gc];
                }
                *(__nv_bfloat162*)&Bs[n][2 * kp] = __floats2bfloat162_rn(v0, v1);
            }
            __syncthreads();

            // ---- two k16 steps ----
#pragma unroll
            for (int ks = 0; ks < 2; ks++) {
                const int ko = ks * 16;
                uint32_t af[4][4];
                uint32_t bfr[4][2];
#pragma unroll
                for (int i = 0; i < 4; i++) {
                    int r = wm * 64 + i * 16 + g;
                    af[i][0] = *(const uint32_t*)&As[r][ko + tq * 2];
                    af[i][1] = *(const uint32_t*)&As[r + 8][ko + tq * 2];
                    af[i][2] = *(const uint32_t*)&As[r][ko + tq * 2 + 8];
                    af[i][3] = *(const uint32_t*)&As[r + 8][ko + tq * 2 + 8];
                }
#pragma unroll
                for (int j = 0; j < 4; j++) {
                    int n = wn * 32 + j * 8 + g;
                    bfr[j][0] = *(const uint32_t*)&Bs[n][ko + tq * 2];
                    bfr[j][1] = *(const uint32_t*)&Bs[n][ko + tq * 2 + 8];
                }
#pragma unroll
                for (int i = 0; i < 4; i++)
#pragma unroll
                    for (int j = 0; j < 4; j++) {
                        asm volatile(
                            "mma.sync.aligned.m16n8k16.row.col.f32.bf16.bf16.f32 "
                            "{%0,%1,%2,%3}, {%4,%5,%6,%7}, {%8,%9}, {%0,%1,%2,%3};\n"
                            : "+f"(acc[i][j][0]), "+f"(acc[i][j][1]),
                              "+f"(acc[i][j][2]), "+f"(acc[i][j][3])
                            : "r"(af[i][0]), "r"(af[i][1]), "r"(af[i][2]), "r"(af[i][3]),
                              "r"(bfr[j][0]), "r"(bfr[j][1]));
                    }
            }
            __syncthreads();
        }
    }

    // ---- epilogue: + bias, optional relu, fp32 or bf16 store ----
#pragma unroll
    for (int i = 0; i < 4; i++) {
        int r0 = row0 + wm * 64 + i * 16 + g;
        int r1 = r0 + 8;
#pragma unroll
        for (int j = 0; j < 4; j++) {
            int c = col0 + wn * 32 + j * 8 + tq * 2;
#pragma unroll
            for (int h = 0; h < 2; h++) {
                int gc = c + h;
                if (gc >= N) continue;
                float b = p.bias[gc];
                if (r0 < M) {
                    float o = acc[i][j][h] + b;
                    if (RELU) o = fmaxf(o, 0.f);
                    if (OUTBF16) ((__nv_bfloat16*)p.C)[(size_t)r0 * N + gc] = __float2bfloat16(o);
                    else         ((float*)p.C)[(size_t)r0 * N + gc] = o;
                }
                if (r1 < M) {
                    float o = acc[i][j][2 + h] + b;
                    if (RELU) o = fmaxf(o, 0.f);
                    if (OUTBF16) ((__nv_bfloat16*)p.C)[(size_t)r1 * N + gc] = __float2bfloat16(o);
                    else         ((float*)p.C)[(size_t)r1 * N + gc] = o;
                }
            }
        }
    }
}

// ---------------------------------------------------------------------------
// Row-wise log_softmax in place, one block (128 threads) per row.
// ---------------------------------------------------------------------------
__inline__ __device__ float warpMax(float v) {
#pragma unroll
    for (int o = 16; o; o >>= 1) v = fmaxf(v, __shfl_xor_sync(0xFFFFFFFFu, v, o));
    return v;
}
__inline__ __device__ float warpSum(float v) {
#pragma unroll
    for (int o = 16; o; o >>= 1) v += __shfl_xor_sync(0xFFFFFFFFu, v, o);
    return v;
}

__global__ void log_softmax_kernel(float* __restrict__ x, int N) {
    float* r = x + (size_t)blockIdx.x * N;
    int t = threadIdx.x;

    float m = -1e30f;
    for (int i = t; i < N; i += 128) m = fmaxf(m, r[i]);
    m = warpMax(m);
    __shared__ float shm[4];
    if ((t & 31) == 0) shm[t >> 5] = m;
    __syncthreads();
    m = fmaxf(fmaxf(shm[0], shm[1]), fmaxf(shm[2], shm[3]));

    float s = 0.f;
    for (int i = t; i < N; i += 128) s += expf(r[i] - m);
    s = warpSum(s);
    __shared__ float shs[4];
    if ((t & 31) == 0) shs[t >> 5] = s;
    __syncthreads();
    s = shs[0] + shs[1] + shs[2] + shs[3];

    float lse = m + logf(s);
    for (int i = t; i < N; i += 128) r[i] = r[i] - lse;
}

// ---------------------------------------------------------------------------
static void run_gemm_fused(bool relu, bool outbf16, const GemmParams& p) {
    dim3 grid((p.N + BN - 1) / BN, (p.M + BM - 1) / BM);
    if (relu) {
        if (outbf16) gemm_fused_kernel<true,  true ><<<grid, 256>>>(p);
        else         gemm_fused_kernel<true,  false><<<grid, 256>>>(p);
    } else {
        if (outbf16) gemm_fused_kernel<false, true ><<<grid, 256>>>(p);
        else         gemm_fused_kernel<false, false><<<grid, 256>>>(p);
    }
}

static void build_csr(const int* src, const int* dst, int E, int n_dst,
                      int* cnt, int* bsum, int* rowptr, int* nextp, int* csr_src) {
    fill0_kernel<<<(n_dst / 4 + 255) / 256, 256>>>((float4*)cnt, n_dst / 4);
    count_int_kernel<<<(E + 255) / 256, 256>>>(dst, E, cnt);
    int nb = (n_dst + SCB - 1) / SCB;
    scan1_kernel<<<nb, SCB>>>(cnt, n_dst, bsum);
    scan2_kernel<<<1, SCB>>>(bsum, nb);
    scan3_kernel<<<nb, SCB>>>(cnt, n_dst, bsum, rowptr, nextp);
    build_csr_kernel<<<(E + 255) / 256, 256>>>(src, dst, E, nextp, csr_src);
}

static void run_gather(const __nv_bfloat16* feat, const int* rowptr, const int* csr_src,
                       int num_dst, __nv_bfloat16* agg) {
    gather_mean_kernel<<<(num_dst + 3) / 4, 256>>>(feat, rowptr, csr_src, num_dst, agg);
}

extern "C" void kernel_launch(void* const* d_in, const int* in_sizes, int n_in,
                              void* d_out, int out_size) {
    const float* x_paper          = (const float*)d_in[0];
    const float* emb_author       = (const float*)d_in[1];
    const float* lin_paper_w      = (const float*)d_in[2];
    const float* lin_paper_b      = (const float*)d_in[3];
    const float* c0_root_paper_w  = (const float*)d_in[4];
    const float* c0_root_paper_b  = (const float*)d_in[5];
    const float* c0_root_author_w = (const float*)d_in[6];
    const float* c0_root_author_b = (const float*)d_in[7];
    const float* c0_rel_writes_w  = (const float*)d_in[8];
    const float* c0_rel_cites_w   = (const float*)d_in[9];
    const float* c0_rel_revw_w    = (const float*)d_in[10];
    const float* c1_root_w        = (const float*)d_in[11];
    const float* c1_root_b        = (const float*)d_in[12];
    const float* c1_rel_writes_w  = (const float*)d_in[13];
    const float* c1_rel_cites_w   = (const float*)d_in[14];
    const int*   writes_src       = (const int*)d_in[15];
    const int*   writes_dst       = (const int*)d_in[16];
    const int*   cites_src        = (const int*)d_in[17];
    const int*   cites_dst        = (const int*)d_in[18];
    const int*   revw_src         = (const int*)d_in[19];
    const int*   revw_dst         = (const int*)d_in[20];

    const int E_W = in_sizes[15];
    const int E_C = in_sizes[17];
    float* out = (float*)d_out;

    __nv_bfloat16 *hp, *outp, *outa, *aggA, *aggB, *emba;
    int *cntW, *cntC, *cntR, *rpW, *rpC, *rpR, *nxW, *nxC, *nxR, *csW, *csC, *csR, *bsum;
    cudaGetSymbolAddress((void**)&hp,   g_hp);
    cudaGetSymbolAddress((void**)&outp, g_outp);
    cudaGetSymbolAddress((void**)&outa, g_outa);
    cudaGetSymbolAddress((void**)&aggA, g_aggA);
    cudaGetSymbolAddress((void**)&aggB, g_aggB);
    cudaGetSymbolAddress((void**)&emba, g_emba);
    cudaGetSymbolAddress((void**)&cntW, g_cntW);
    cudaGetSymbolAddress((void**)&cntC, g_cntC);
    cudaGetSymbolAddress((void**)&cntR, g_cntR);
    cudaGetSymbolAddress((void**)&rpW,  g_rpW);
    cudaGetSymbolAddress((void**)&rpC,  g_rpC);
    cudaGetSymbolAddress((void**)&rpR,  g_rpR);
    cudaGetSymbolAddress((void**)&nxW,  g_nxW);
    cudaGetSymbolAddress((void**)&nxC,  g_nxC);
    cudaGetSymbolAddress((void**)&nxR,  g_nxR);
    cudaGetSymbolAddress((void**)&csW,  g_csW);
    cudaGetSymbolAddress((void**)&csC,  g_csC);
    cudaGetSymbolAddress((void**)&csR,  g_csR);
    cudaGetSymbolAddress((void**)&bsum, g_bsum);

    // CSRs (reused by both layers)
    build_csr(writes_src, writes_dst, E_W, P_N, cntW, bsum, rpW, nxW, csW);
    build_csr(cites_src,  cites_dst,  E_C, P_N, cntC, bsum, rpC, nxC, csC);
    build_csr(revw_src,   revw_dst,   E_W, A_N, cntR, bsum, rpR, nxR, csR);

    // emb_author -> bf16
    f2b_kernel<<<((A_N * H_C / 4) + 255) / 256, 256>>>(
        (const float4*)emb_author, (uint2*)emba, A_N * H_C / 4);

    // 1) hp = bf16(x_paper @ lin_paper_w + b)
    {
        GemmParams p = {};
        p.A[0] = x_paper; p.B[0] = lin_paper_w; p.K[0] = IN_C; p.abf16[0] = 0;
        p.nseg = 1; p.bias = lin_paper_b; p.C = hp; p.M = P_N; p.N = H_C;
        run_gemm_fused(false, true, p);
    }

    // 2) layer-0 gathers for paper dst
    run_gather(emba, rpW, csW, P_N, aggA);   // writes: authors -> papers
    run_gather(hp,   rpC, csC, P_N, aggB);   // cites:  papers  -> papers

    // 3) outp = relu(hp@W + aggA@Ww + aggB@Wc + b)   [bf16]
    {
        GemmParams p = {};
        p.A[0] = hp;   p.B[0] = c0_root_paper_w; p.K[0] = H_C; p.abf16[0] = 1;
        p.A[1] = aggA; p.B[1] = c0_rel_writes_w; p.K[1] = H_C; p.abf16[1] = 1;
        p.A[2] = aggB; p.B[2] = c0_rel_cites_w;  p.K[2] = H_C; p.abf16[2] = 1;
        p.nseg = 3; p.bias = c0_root_paper_b; p.C = outp; p.M = P_N; p.N = H_C;
        run_gemm_fused(true, true, p);
    }

    // 4) author side
    run_gather(hp, rpR, csR, A_N, aggA);     // revw: papers -> authors
    {
        GemmParams p = {};
        p.A[0] = emba; p.B[0] = c0_root_author_w; p.K[0] = H_C; p.abf16[0] = 1;
        p.A[1] = aggA; p.B[1] = c0_rel_revw_w;    p.K[1] = H_C; p.abf16[1] = 1;
        p.nseg = 2; p.bias = c0_root_author_b; p.C = outa; p.M = A_N; p.N = H_C;
        run_gemm_fused(true, true, p);
    }

    // 5) layer-1 gathers
    run_gather(outa, rpW, csW, P_N, aggA);
    run_gather(outp, rpC, csC, P_N, aggB);

    // 6) out = outp@W1 + aggA@W1w + aggB@W1c + b   [fp32]
    {
        GemmParams p = {};
        p.A[0] = outp; p.B[0] = c1_root_w;       p.K[0] = H_C; p.abf16[0] = 1;
        p.A[1] = aggA; p.B[1] = c1_rel_writes_w; p.K[1] = H_C; p.abf16[1] = 1;
        p.A[2] = aggB; p.B[2] = c1_rel_cites_w;  p.K[2] = H_C; p.abf16[2] = 1;
        p.nseg = 3; p.bias = c1_root_b; p.C = out; p.M = P_N; p.N = OUT_C;
        run_gemm_fused(false, false, p);
    }

    // 7) log_softmax in place
    log_softmax_kernel<<<P_N, 128>>>(out, OUT_C);
}

// round 7
// speedup vs baseline: 4.8289x; 1.4184x over previous
#include <cuda_runtime.h>
#include <cuda_bf16.h>
#include <cstdint>

// ---------------------------------------------------------------------------
// RGCN forward. CSR gather-mean (bf16), pipelined bf16 HMMA GEMMs with
// cp.async double buffering + ldmatrix fragment loads.
// P=100000, A=50000, IN=128, H=256, OUT=349
// ---------------------------------------------------------------------------

#define P_N   100000
#define A_N   50000
#define IN_C  128
#define H_C   256
#define OUT_C 349
#define EW_MAX 600000
#define EC_MAX 1000000

// bf16 feature buffers
__device__ __nv_bfloat16 g_hp  [(size_t)P_N * H_C];
__device__ __nv_bfloat16 g_outp[(size_t)P_N * H_C];
__device__ __nv_bfloat16 g_outa[(size_t)A_N * H_C];
__device__ __nv_bfloat16 g_aggA[(size_t)P_N * H_C];
__device__ __nv_bfloat16 g_aggB[(size_t)P_N * H_C];
__device__ __nv_bfloat16 g_emba[(size_t)A_N * H_C];
__device__ __nv_bfloat16 g_xb  [(size_t)P_N * IN_C];

// bf16 weights (padded to Npad columns)
__device__ __nv_bfloat16 g_wlin [IN_C * H_C];
__device__ __nv_bfloat16 g_w0rp [H_C * H_C];
__device__ __nv_bfloat16 g_w0ra [H_C * H_C];
__device__ __nv_bfloat16 g_w0w  [H_C * H_C];
__device__ __nv_bfloat16 g_w0c  [H_C * H_C];
__device__ __nv_bfloat16 g_w0r  [H_C * H_C];
__device__ __nv_bfloat16 g_w1rt [H_C * 352];
__device__ __nv_bfloat16 g_w1w  [H_C * 352];
__device__ __nv_bfloat16 g_w1c  [H_C * 352];

// CSR scratch
__device__ int g_cntW[P_N], g_cntC[P_N], g_cntR[A_N];
__device__ int g_rpW[P_N + 1], g_rpC[P_N + 1], g_rpR[A_N + 1];
__device__ int g_nxW[P_N], g_nxC[P_N], g_nxR[A_N];
__device__ int g_csW[EW_MAX], g_csC[EC_MAX], g_csR[EW_MAX];
__device__ int g_bsum[1024];

// ---------------------------------------------------------------------------
__global__ void fill0_kernel(float4* __restrict__ p, int n4) {
    int i = blockIdx.x * blockDim.x + threadIdx.x;
    if (i < n4) p[i] = make_float4(0.f, 0.f, 0.f, 0.f);
}

__global__ void count_int_kernel(const int* __restrict__ dst, int E, int* __restrict__ cnt) {
    int i = blockIdx.x * blockDim.x + threadIdx.x;
    if (i < E) atomicAdd(&cnt[dst[i]], 1);
}

// ---------------------------------------------------------------------------
#define SCB 1024

__global__ void scan1_kernel(const int* __restrict__ cnt, int n, int* __restrict__ bsum) {
    __shared__ int sh[SCB];
    int tid = threadIdx.x;
    int i = blockIdx.x * SCB + tid;
    sh[tid] = (i < n) ? cnt[i] : 0;
    __syncthreads();
    for (int off = SCB / 2; off; off >>= 1) {
        if (tid < off) sh[tid] += sh[tid + off];
        __syncthreads();
    }
    if (!tid) bsum[blockIdx.x] = sh[0];
}

__global__ void scan2_kernel(int* __restrict__ bsum, int nb) {
    __shared__ int sh[SCB];
    int tid = threadIdx.x;
    int v = (tid < nb) ? bsum[tid] : 0;
    sh[tid] = v;
    __syncthreads();
    for (int off = 1; off < SCB; off <<= 1) {
        int a = (tid >= off) ? sh[tid - off] : 0;
        __syncthreads();
        sh[tid] += a;
        __syncthreads();
    }
    if (tid < nb) bsum[tid] = sh[tid] - v;
}

__global__ void scan3_kernel(const int* __restrict__ cnt, int n, const int* __restrict__ bsum,
                             int* __restrict__ rowptr, int* __restrict__ nextp) {
    __shared__ int sh[SCB];
    int tid = threadIdx.x;
    int i = blockIdx.x * SCB + tid;
    int v = (i < n) ? cnt[i] : 0;
    sh[tid] = v;
    __syncthreads();
    for (int off = 1; off < SCB; off <<= 1) {
        int a = (tid >= off) ? sh[tid - off] : 0;
        __syncthreads();
        sh[tid] += a;
        __syncthreads();
    }
    int excl = sh[tid] - v + bsum[blockIdx.x];
    if (i < n) { rowptr[i] = excl; nextp[i] = excl; }
    if (i == n - 1) rowptr[n] = excl + v;
}

__global__ void build_csr_kernel(const int* __restrict__ src, const int* __restrict__ dst,
                                 int E, int* __restrict__ nextp, int* __restrict__ csr_src) {
    int i = blockIdx.x * blockDim.x + threadIdx.x;
    if (i < E) {
        int p = atomicAdd(&nextp[dst[i]], 1);
        csr_src[p] = src[i];
    }
}

// ---------------------------------------------------------------------------
__global__ void f2b_kernel(const float4* __restrict__ in, uint2* __restrict__ out, int n4) {
    int i = blockIdx.x * blockDim.x + threadIdx.x;
    if (i >= n4) return;
    float4 v = in[i];
    __nv_bfloat162 a = __floats2bfloat162_rn(v.x, v.y);
    __nv_bfloat162 b = __floats2bfloat162_rn(v.z, v.w);
    uint2 o;
    o.x = *(uint32_t*)&a;
    o.y = *(uint32_t*)&b;
    out[i] = o;
}

// fp32 [K][N] -> bf16 [K][Npad] zero-padded
__global__ void w2b_kernel(const float* __restrict__ in, __nv_bfloat16* __restrict__ out,
                           int K, int N, int Npad) {
    int i = blockIdx.x * blockDim.x + threadIdx.x;
    int total = K * Npad;
    if (i >= total) return;
    int k = i / Npad, c = i - k * Npad;
    out[i] = __float2bfloat16(c < N ? in[k * N + c] : 0.f);
}

// ---------------------------------------------------------------------------
// Gather-mean (bf16 in/out, fp32 accumulation). 64 threads per dst row.
// ---------------------------------------------------------------------------
__global__ void gather_mean_kernel(const __nv_bfloat16* __restrict__ feat,
                                   const int* __restrict__ rowptr,
                                   const int* __restrict__ csr_src,
                                   int num_dst,
                                   __nv_bfloat16* __restrict__ agg) {
    int group = blockIdx.x * 4 + (threadIdx.x >> 6);
    int lane  = threadIdx.x & 63;
    if (group >= num_dst) return;
    int beg = rowptr[group], end = rowptr[group + 1];
    int c4 = lane * 4;

    float s0 = 0.f, s1 = 0.f, s2 = 0.f, s3 = 0.f;
    int i = beg;
    for (; i + 1 < end; i += 2) {
        int sa = csr_src[i];
        int sb = csr_src[i + 1];
        uint2 ua = *(const uint2*)&feat[(size_t)sa * H_C + c4];
        uint2 ub = *(const uint2*)&feat[(size_t)sb * H_C + c4];
        float2 a0 = __bfloat1622float2(*(__nv_bfloat162*)&ua.x);
        float2 a1 = __bfloat1622float2(*(__nv_bfloat162*)&ua.y);
        float2 b0 = __bfloat1622float2(*(__nv_bfloat162*)&ub.x);
        float2 b1 = __bfloat1622float2(*(__nv_bfloat162*)&ub.y);
        s0 += a0.x + b0.x; s1 += a0.y + b0.y;
        s2 += a1.x + b1.x; s3 += a1.y + b1.y;
    }
    if (i < end) {
        int sa = csr_src[i];
        uint2 ua = *(const uint2*)&feat[(size_t)sa * H_C + c4];
        float2 a0 = __bfloat1622float2(*(__nv_bfloat162*)&ua.x);
        float2 a1 = __bfloat1622float2(*(__nv_bfloat162*)&ua.y);
        s0 += a0.x; s1 += a0.y; s2 += a1.x; s3 += a1.y;
    }
    float inv = (end > beg) ? 1.0f / (float)(end - beg) : 0.f;
    __nv_bfloat162 o0 = __floats2bfloat162_rn(s0 * inv, s1 * inv);
    __nv_bfloat162 o1 = __floats2bfloat162_rn(s2 * inv, s3 * inv);
    uint2 o;
    o.x = *(uint32_t*)&o0;
    o.y = *(uint32_t*)&o1;
    *(uint2*)&agg[(size_t)group * H_C + c4] = o;
}

// ---------------------------------------------------------------------------
// Pipelined fused multi-segment bf16 GEMM.
//   C[M,N] = sum_s A_s[M,K_s] @ B_s[K_s,Npad(:N)] + bias  [relu]
// BM=BN=128, BK=32. cp.async double buffering; ldmatrix frag loads.
// ---------------------------------------------------------------------------
#define BM 128
#define BN 128
#define BK 32
#define PK 40    // A smem row stride (bf16), conflict-free LDSM
#define PN 136   // B smem row stride (bf16), conflict-free LDSM.trans
#define A_ELEMS (BM * PK)
#define B_ELEMS (BK * PN)
#define STAGE_ELEMS (A_ELEMS + B_ELEMS)
#define STAGE_BYTES (STAGE_ELEMS * 2)
#define A_BYTES (A_ELEMS * 2)

struct GemmParams {
    const __nv_bfloat16* A[3];
    const __nv_bfloat16* B[3];
    int          K[3];
    int          nseg;
    const float* bias;
    void*        C;
    int          M, N, Npad;
};

__device__ __forceinline__ void cp16(uint32_t dst, const void* src, bool pred) {
    int sz = pred ? 16 : 0;
    asm volatile("cp.async.cg.shared.global [%0], [%1], 16, %2;"
                 :: "r"(dst), "l"(src), "r"(sz));
}

template<bool RELU, bool OUTBF16>
__global__ __launch_bounds__(256, 2)
void gemm_fused_kernel(GemmParams p) {
    __shared__ __align__(16) __nv_bfloat16 sm[2 * STAGE_ELEMS];

    const int t    = threadIdx.x;
    const int lane = t & 31;
    const int w    = t >> 5;
    const int wm   = w & 1;
    const int wn   = w >> 1;
    const int g    = lane >> 2;
    const int tq   = lane & 3;
    const int row0 = blockIdx.y * BM;
    const int col0 = blockIdx.x * BN;
    const int M = p.M, N = p.N, Npad = p.Npad;
    const int nseg = p.nseg;

    // tiles per segment (0 for unused segments)
    const int kt0 = p.K[0] / BK;
    const int kt1 = (nseg > 1) ? p.K[1] / BK : 0;
    const int kt2 = (nseg > 2) ? p.K[2] / BK : 0;
    const int total = kt0 + kt1 + kt2;

    const uint32_t smBase = (uint32_t)__cvta_generic_to_shared(sm);

    // ldmatrix per-lane base addresses (stage 0)
    const uint32_t aBase = smBase +
        (uint32_t)(((wm * 64 + (lane & 15)) * PK + ((lane >> 4) << 3)) << 1);
    const uint32_t bBase = smBase + A_BYTES +
        (uint32_t)(((lane & 15) * PN + wn * 32 + ((lane >> 4) << 3)) << 1);

    float acc[4][4][4];
#pragma unroll
    for (int i = 0; i < 4; i++)
#pragma unroll
        for (int j = 0; j < 4; j++)
#pragma unroll
            for (int v = 0; v < 4; v++) acc[i][j][v] = 0.f;

    // issue cp.async loads for global tile `ti` into stage `st`.
    // Bounded segment walk: at most 2 predicated advances, can never spin.
    auto issue = [&](int ti, int st) {
        int s = 0, rem = ti;
        if (rem >= kt0)            { rem -= kt0; s = 1; }
        if (s == 1 && rem >= kt1)  { rem -= kt1; s = 2; }
        int k0 = rem * BK;
        const __nv_bfloat16* A = p.A[s];
        const __nv_bfloat16* B = p.B[s];
        int K = p.K[s];
        uint32_t sb = smBase + st * STAGE_BYTES;
        // A tile: 128 x 32, 512 16B chunks
#pragma unroll
        for (int it = 0; it < 2; it++) {
            int idx = t + it * 256;
            int r   = idx >> 2;
            int c8  = (idx & 3) * 8;
            int gr  = row0 + r;
            bool ok = (gr < M);
            int  sr = ok ? gr : 0;            // clamp: never form an OOB address
            uint32_t dst = sb + (uint32_t)((r * PK + c8) << 1);
            cp16(dst, A + (size_t)sr * K + k0 + c8, ok);
        }
        // B tile: 32 x 128, 512 16B chunks
#pragma unroll
        for (int it = 0; it < 2; it++) {
            int idx = t + it * 256;
            int kr  = idx >> 4;
            int c8  = (idx & 15) * 8;
            int gc  = col0 + c8;
            bool ok = (gc < Npad);
            int  sc = ok ? gc : 0;
            uint32_t dst = sb + A_BYTES + (uint32_t)((kr * PN + c8) << 1);
            cp16(dst, B + (size_t)(k0 + kr) * Npad + sc, ok);
        }
        asm volatile("cp.async.commit_group;");
    };

    issue(0, 0);

    for (int ti = 0; ti < total; ti++) {
        if (ti + 1 < total) {
            issue(ti + 1, (ti + 1) & 1);
            asm volatile("cp.async.wait_group 1;");
        } else {
            asm volatile("cp.async.wait_group 0;");
        }
        __syncthreads();

        const uint32_t so = (uint32_t)((ti & 1) * STAGE_BYTES);
#pragma unroll
        for (int ks = 0; ks < 2; ks++) {
            const int ko = ks * 16;
            uint32_t a[4][4];
#pragma unroll
            for (int i = 0; i < 4; i++) {
                uint32_t addr = aBase + so + (uint32_t)(((i * 16) * PK + ko) << 1);
                asm volatile("ldmatrix.sync.aligned.m8n8.x4.shared.b16 {%0,%1,%2,%3}, [%4];"
                             : "=r"(a[i][0]), "=r"(a[i][1]), "=r"(a[i][2]), "=r"(a[i][3])
                             : "r"(addr));
            }
            uint32_t b[2][4];
#pragma unroll
            for (int jj = 0; jj < 2; jj++) {
                uint32_t addr = bBase + so + (uint32_t)((ko * PN + jj * 16) << 1);
                asm volatile("ldmatrix.sync.aligned.m8n8.x4.trans.shared.b16 {%0,%1,%2,%3}, [%4];"
                             : "=r"(b[jj][0]), "=r"(b[jj][1]), "=r"(b[jj][2]), "=r"(b[jj][3])
                             : "r"(addr));
            }
#pragma unroll
            for (int i = 0; i < 4; i++)
#pragma unroll
                for (int j = 0; j < 4; j++) {
                    uint32_t b0 = b[j >> 1][(j & 1) * 2];
                    uint32_t b1 = b[j >> 1][(j & 1) * 2 + 1];
                    asm volatile(
                        "mma.sync.aligned.m16n8k16.row.col.f32.bf16.bf16.f32 "
                        "{%0,%1,%2,%3}, {%4,%5,%6,%7}, {%8,%9}, {%0,%1,%2,%3};\n"
                        : "+f"(acc[i][j][0]), "+f"(acc[i][j][1]),
                          "+f"(acc[i][j][2]), "+f"(acc[i][j][3])
                        : "r"(a[i][0]), "r"(a[i][1]), "r"(a[i][2]), "r"(a[i][3]),
                          "r"(b0), "r"(b1));
                }
        }
        __syncthreads();
    }

    // ---- epilogue ----
#pragma unroll
    for (int i = 0; i < 4; i++) {
        int r0 = row0 + wm * 64 + i * 16 + g;
        int r1 = r0 + 8;
#pragma unroll
        for (int j = 0; j < 4; j++) {
            int c = col0 + wn * 32 + j * 8 + tq * 2;
#pragma unroll
            for (int h = 0; h < 2; h++) {
                int gc = c + h;
                if (gc >= N) continue;
                float bv = p.bias[gc];
                if (r0 < M) {
                    float o = acc[i][j][h] + bv;
                    if (RELU) o = fmaxf(o, 0.f);
                    if (OUTBF16) ((__nv_bfloat16*)p.C)[(size_t)r0 * N + gc] = __float2bfloat16(o);
                    else         ((float*)p.C)[(size_t)r0 * N + gc] = o;
                }
                if (r1 < M) {
                    float o = acc[i][j][2 + h] + bv;
                    if (RELU) o = fmaxf(o, 0.f);
                    if (OUTBF16) ((__nv_bfloat16*)p.C)[(size_t)r1 * N + gc] = __float2bfloat16(o);
                    else         ((float*)p.C)[(size_t)r1 * N + gc] = o;
                }
            }
        }
    }
}

// ---------------------------------------------------------------------------
__inline__ __device__ float warpMax(float v) {
#pragma unroll
    for (int o = 16; o; o >>= 1) v = fmaxf(v, __shfl_xor_sync(0xFFFFFFFFu, v, o));
    return v;
}
__inline__ __device__ float warpSum(float v) {
#pragma unroll
    for (int o = 16; o; o >>= 1) v += __shfl_xor_sync(0xFFFFFFFFu, v, o);
    return v;
}

__global__ void log_softmax_kernel(float* __restrict__ x, int N) {
    float* r = x + (size_t)blockIdx.x * N;
    int t = threadIdx.x;

    float m = -1e30f;
    for (int i = t; i < N; i += 128) m = fmaxf(m, r[i]);
    m = warpMax(m);
    __shared__ float shm[4];
    if ((t & 31) == 0) shm[t >> 5] = m;
    __syncthreads();
    m = fmaxf(fmaxf(shm[0], shm[1]), fmaxf(shm[2], shm[3]));

    float s = 0.f;
    for (int i = t; i < N; i += 128) s += expf(r[i] - m);
    s = warpSum(s);
    __shared__ float shs[4];
    if ((t & 31) == 0) shs[t >> 5] = s;
    __syncthreads();
    s = shs[0] + shs[1] + shs[2] + shs[3];

    float lse = m + logf(s);
    for (int i = t; i < N; i += 128) r[i] = r[i] - lse;
}

// ---------------------------------------------------------------------------
static void run_gemm_fused(bool relu, bool outbf16, const GemmParams& p) {
    dim3 grid((p.N + BN - 1) / BN, (p.M + BM - 1) / BM);
    if (relu) {
        if (outbf16) gemm_fused_kernel<true,  true ><<<grid, 256>>>(p);
        else         gemm_fused_kernel<true,  false><<<grid, 256>>>(p);
    } else {
        if (outbf16) gemm_fused_kernel<false, true ><<<grid, 256>>>(p);
        else         gemm_fused_kernel<false, false><<<grid, 256>>>(p);
    }
}

static void build_csr(const int* src, const int* dst, int E, int n_dst,
                      int* cnt, int* bsum, int* rowptr, int* nextp, int* csr_src) {
    fill0_kernel<<<(n_dst / 4 + 255) / 256, 256>>>((float4*)cnt, n_dst / 4);
    count_int_kernel<<<(E + 255) / 256, 256>>>(dst, E, cnt);
    int nb = (n_dst + SCB - 1) / SCB;
    scan1_kernel<<<nb, SCB>>>(cnt, n_dst, bsum);
    scan2_kernel<<<1, SCB>>>(bsum, nb);
    scan3_kernel<<<nb, SCB>>>(cnt, n_dst, bsum, rowptr, nextp);
    build_csr_kernel<<<(E + 255) / 256, 256>>>(src, dst, E, nextp, csr_src);
}

static void run_gather(const __nv_bfloat16* feat, const int* rowptr, const int* csr_src,
                       int num_dst, __nv_bfloat16* agg) {
    gather_mean_kernel<<<(num_dst + 3) / 4, 256>>>(feat, rowptr, csr_src, num_dst, agg);
}

static void run_w2b(const float* in, __nv_bfloat16* out, int K, int N, int Npad) {
    int total = K * Npad;
    w2b_kernel<<<(total + 255) / 256, 256>>>(in, out, K, N, Npad);
}

extern "C" void kernel_launch(void* const* d_in, const int* in_sizes, int n_in,
                              void* d_out, int out_size) {
    const float* x_paper          = (const float*)d_in[0];
    const float* emb_author       = (const float*)d_in[1];
    const float* lin_paper_w      = (const float*)d_in[2];
    const float* lin_paper_b      = (const float*)d_in[3];
    const float* c0_root_paper_w  = (const float*)d_in[4];
    const float* c0_root_paper_b  = (const float*)d_in[5];
    const float* c0_root_author_w = (const float*)d_in[6];
    const float* c0_root_author_b = (const float*)d_in[7];
    const float* c0_rel_writes_w  = (const float*)d_in[8];
    const float* c0_rel_cites_w   = (const float*)d_in[9];
    const float* c0_rel_revw_w    = (const float*)d_in[10];
    const float* c1_root_w        = (const float*)d_in[11];
    const float* c1_root_b        = (const float*)d_in[12];
    const float* c1_rel_writes_w  = (const float*)d_in[13];
    const float* c1_rel_cites_w   = (const float*)d_in[14];
    const int*   writes_src       = (const int*)d_in[15];
    const int*   writes_dst       = (const int*)d_in[16];
    const int*   cites_src        = (const int*)d_in[17];
    const int*   cites_dst        = (const int*)d_in[18];
    const int*   revw_src         = (const int*)d_in[19];
    const int*   revw_dst         = (const int*)d_in[20];

    const int E_W = in_sizes[15];
    const int E_C = in_sizes[17];
    float* out = (float*)d_out;

    __nv_bfloat16 *hp, *outp, *outa, *aggA, *aggB, *emba, *xb;
    __nv_bfloat16 *wlin, *w0rp, *w0ra, *w0w, *w0c, *w0r, *w1rt, *w1w, *w1c;
    int *cntW, *cntC, *cntR, *rpW, *rpC, *rpR, *nxW, *nxC, *nxR, *csW, *csC, *csR, *bsum;
    cudaGetSymbolAddress((void**)&hp,   g_hp);
    cudaGetSymbolAddress((void**)&outp, g_outp);
    cudaGetSymbolAddress((void**)&outa, g_outa);
    cudaGetSymbolAddress((void**)&aggA, g_aggA);
    cudaGetSymbolAddress((void**)&aggB, g_aggB);
    cudaGetSymbolAddress((void**)&emba, g_emba);
    cudaGetSymbolAddress((void**)&xb,   g_xb);
    cudaGetSymbolAddress((void**)&wlin, g_wlin);
    cudaGetSymbolAddress((void**)&w0rp, g_w0rp);
    cudaGetSymbolAddress((void**)&w0ra, g_w0ra);
    cudaGetSymbolAddress((void**)&w0w,  g_w0w);
    cudaGetSymbolAddress((void**)&w0c,  g_w0c);
    cudaGetSymbolAddress((void**)&w0r,  g_w0r);
    cudaGetSymbolAddress((void**)&w1rt, g_w1rt);
    cudaGetSymbolAddress((void**)&w1w,  g_w1w);
    cudaGetSymbolAddress((void**)&w1c,  g_w1c);
    cudaGetSymbolAddress((void**)&cntW, g_cntW);
    cudaGetSymbolAddress((void**)&cntC, g_cntC);
    cudaGetSymbolAddress((void**)&cntR, g_cntR);
    cudaGetSymbolAddress((void**)&rpW,  g_rpW);
    cudaGetSymbolAddress((void**)&rpC,  g_rpC);
    cudaGetSymbolAddress((void**)&rpR,  g_rpR);
    cudaGetSymbolAddress((void**)&nxW,  g_nxW);
    cudaGetSymbolAddress((void**)&nxC,  g_nxC);
    cudaGetSymbolAddress((void**)&nxR,  g_nxR);
    cudaGetSymbolAddress((void**)&csW,  g_csW);
    cudaGetSymbolAddress((void**)&csC,  g_csC);
    cudaGetSymbolAddress((void**)&csR,  g_csR);
    cudaGetSymbolAddress((void**)&bsum, g_bsum);

    // CSRs
    build_csr(writes_src, writes_dst, E_W, P_N, cntW, bsum, rpW, nxW, csW);
    build_csr(cites_src,  cites_dst,  E_C, P_N, cntC, bsum, rpC, nxC, csC);
    build_csr(revw_src,   revw_dst,   E_W, A_N, cntR, bsum, rpR, nxR, csR);

    // bf16 conversions
    f2b_kernel<<<((A_N * H_C / 4) + 255) / 256, 256>>>(
        (const float4*)emb_author, (uint2*)emba, A_N * H_C / 4);
    f2b_kernel<<<((P_N * IN_C / 4) + 255) / 256, 256>>>(
        (const float4*)x_paper, (uint2*)xb, P_N * IN_C / 4);
    run_w2b(lin_paper_w,      wlin, IN_C, H_C, H_C);
    run_w2b(c0_root_paper_w,  w0rp, H_C, H_C, H_C);
    run_w2b(c0_root_author_w, w0ra, H_C, H_C, H_C);
    run_w2b(c0_rel_writes_w,  w0w,  H_C, H_C, H_C);
    run_w2b(c0_rel_cites_w,   w0c,  H_C, H_C, H_C);
    run_w2b(c0_rel_revw_w,    w0r,  H_C, H_C, H_C);
    run_w2b(c1_root_w,        w1rt, H_C, OUT_C, 352);
    run_w2b(c1_rel_writes_w,  w1w,  H_C, OUT_C, 352);
    run_w2b(c1_rel_cites_w,   w1c,  H_C, OUT_C, 352);

    // 1) hp = bf16(x_paper @ lin_paper_w + b)
    {
        GemmParams p = {};
        p.A[0] = xb; p.B[0] = wlin; p.K[0] = IN_C;
        p.nseg = 1; p.bias = lin_paper_b; p.C = hp; p.M = P_N; p.N = H_C; p.Npad = H_C;
        run_gemm_fused(false, true, p);
    }

    // 2) layer-0 gathers for paper dst
    run_gather(emba, rpW, csW, P_N, aggA);
    run_gather(hp,   rpC, csC, P_N, aggB);

    // 3) outp = relu(hp@W + aggA@Ww + aggB@Wc + b)
    {
        GemmParams p = {};
        p.A[0] = hp;   p.B[0] = w0rp; p.K[0] = H_C;
        p.A[1] = aggA; p.B[1] = w0w;  p.K[1] = H_C;
        p.A[2] = aggB; p.B[2] = w0c;  p.K[2] = H_C;
        p.nseg = 3; p.bias = c0_root_paper_b; p.C = outp; p.M = P_N; p.N = H_C; p.Npad = H_C;
        run_gemm_fused(true, true, p);
    }

    // 4) author side
    run_gather(hp, rpR, csR, A_N, aggA);
    {
        GemmParams p = {};
        p.A[0] = emba; p.B[0] = w0ra; p.K[0] = H_C;
        p.A[1] = aggA; p.B[1] = w0r;  p.K[1] = H_C;
        p.nseg = 2; p.bias = c0_root_author_b; p.C = outa; p.M = A_N; p.N = H_C; p.Npad = H_C;
        run_gemm_fused(true, true, p);
    }

    // 5) layer-1 gathers
    run_gather(outa, rpW, csW, P_N, aggA);
    run_gather(outp, rpC, csC, P_N, aggB);

    // 6) out = outp@W1 + aggA@W1w + aggB@W1c + b   [fp32]
    {
        GemmParams p = {};
        p.A[0] = outp; p.B[0] = w1rt; p.K[0] = H_C;
        p.A[1] = aggA; p.B[1] = w1w;  p.K[1] = H_C;
        p.A[2] = aggB; p.B[2] = w1c;  p.K[2] = H_C;
        p.nseg = 3; p.bias = c1_root_b; p.C = out; p.M = P_N; p.N = OUT_C; p.Npad = 352;
        run_gemm_fused(false, false, p);
    }

    // 7) log_softmax in place
    log_softmax_kernel<<<P_N, 128>>>(out, OUT_C);
}

// round 8
// speedup vs baseline: 8.3551x; 1.7302x over previous
#include <cuda_runtime.h>
#include <cuda_bf16.h>
#include <cstdint>

// ---------------------------------------------------------------------------
// RGCN forward. CSR gather-mean (bf16), pipelined bf16 HMMA GEMMs:
// BK=64 double-buffered cp.async, ldmatrix frags, smem-staged epilogues.
// P=100000, A=50000, IN=128, H=256, OUT=349
// ---------------------------------------------------------------------------

#define P_N   100000
#define A_N   50000
#define IN_C  128
#define H_C   256
#define OUT_C 349
#define EW_MAX 600000
#define EC_MAX 1000000

// bf16 feature buffers
__device__ __nv_bfloat16 g_hp  [(size_t)P_N * H_C];
__device__ __nv_bfloat16 g_outp[(size_t)P_N * H_C];
__device__ __nv_bfloat16 g_outa[(size_t)A_N * H_C];
__device__ __nv_bfloat16 g_aggA[(size_t)P_N * H_C];
__device__ __nv_bfloat16 g_aggB[(size_t)P_N * H_C];
__device__ __nv_bfloat16 g_emba[(size_t)A_N * H_C];
__device__ __nv_bfloat16 g_xb  [(size_t)P_N * IN_C];

// bf16 weights (padded to Npad columns)
__device__ __nv_bfloat16 g_wlin [IN_C * H_C];
__device__ __nv_bfloat16 g_w0rp [H_C * H_C];
__device__ __nv_bfloat16 g_w0ra [H_C * H_C];
__device__ __nv_bfloat16 g_w0w  [H_C * H_C];
__device__ __nv_bfloat16 g_w0c  [H_C * H_C];
__device__ __nv_bfloat16 g_w0r  [H_C * H_C];
__device__ __nv_bfloat16 g_w1rt [H_C * 352];
__device__ __nv_bfloat16 g_w1w  [H_C * 352];
__device__ __nv_bfloat16 g_w1c  [H_C * 352];

// CSR scratch
__device__ int g_cntW[P_N], g_cntC[P_N], g_cntR[A_N];
__device__ int g_rpW[P_N + 1], g_rpC[P_N + 1], g_rpR[A_N + 1];
__device__ int g_nxW[P_N], g_nxC[P_N], g_nxR[A_N];
__device__ int g_csW[EW_MAX], g_csC[EC_MAX], g_csR[EW_MAX];
__device__ int g_bsum[1024];

// ---------------------------------------------------------------------------
// Zero the three count arrays in one launch
__global__ void fill3_kernel(int4* a, int na4, int4* b, int nb4, int4* c, int nc4) {
    int i = blockIdx.x * blockDim.x + threadIdx.x;
    int4 z = make_int4(0, 0, 0, 0);
    if (i < na4) a[i] = z;
    else if (i < na4 + nb4) b[i - na4] = z;
    else if (i < na4 + nb4 + nc4) c[i - na4 - nb4] = z;
}

__global__ void count_int_kernel(const int* __restrict__ dst, int E, int* __restrict__ cnt) {
    int i = blockIdx.x * blockDim.x + threadIdx.x;
    if (i < E) atomicAdd(&cnt[dst[i]], 1);
}

// ---------------------------------------------------------------------------
#define SCB 1024

__global__ void scan1_kernel(const int* __restrict__ cnt, int n, int* __restrict__ bsum) {
    __shared__ int sh[SCB];
    int tid = threadIdx.x;
    int i = blockIdx.x * SCB + tid;
    sh[tid] = (i < n) ? cnt[i] : 0;
    __syncthreads();
    for (int off = SCB / 2; off; off >>= 1) {
        if (tid < off) sh[tid] += sh[tid + off];
        __syncthreads();
    }
    if (!tid) bsum[blockIdx.x] = sh[0];
}

__global__ void scan2_kernel(int* __restrict__ bsum, int nb) {
    __shared__ int sh[SCB];
    int tid = threadIdx.x;
    int v = (tid < nb) ? bsum[tid] : 0;
    sh[tid] = v;
    __syncthreads();
    for (int off = 1; off < SCB; off <<= 1) {
        int a = (tid >= off) ? sh[tid - off] : 0;
        __syncthreads();
        sh[tid] += a;
        __syncthreads();
    }
    if (tid < nb) bsum[tid] = sh[tid] - v;
}

__global__ void scan3_kernel(const int* __restrict__ cnt, int n, const int* __restrict__ bsum,
                             int* __restrict__ rowptr, int* __restrict__ nextp) {
    __shared__ int sh[SCB];
    int tid = threadIdx.x;
    int i = blockIdx.x * SCB + tid;
    int v = (i < n) ? cnt[i] : 0;
    sh[tid] = v;
    __syncthreads();
    for (int off = 1; off < SCB; off <<= 1) {
        int a = (tid >= off) ? sh[tid - off] : 0;
        __syncthreads();
        sh[tid] += a;
        __syncthreads();
    }
    int excl = sh[tid] - v + bsum[blockIdx.x];
    if (i < n) { rowptr[i] = excl; nextp[i] = excl; }
    if (i == n - 1) rowptr[n] = excl + v;
}

__global__ void build_csr_kernel(const int* __restrict__ src, const int* __restrict__ dst,
                                 int E, int* __restrict__ nextp, int* __restrict__ csr_src) {
    int i = blockIdx.x * blockDim.x + threadIdx.x;
    if (i < E) {
        int p = atomicAdd(&nextp[dst[i]], 1);
        csr_src[p] = src[i];
    }
}

// ---------------------------------------------------------------------------
__global__ void f2b_kernel(const float4* __restrict__ in, uint2* __restrict__ out, int n4) {
    int i = blockIdx.x * blockDim.x + threadIdx.x;
    if (i >= n4) return;
    float4 v = in[i];
    __nv_bfloat162 a = __floats2bfloat162_rn(v.x, v.y);
    __nv_bfloat162 b = __floats2bfloat162_rn(v.z, v.w);
    uint2 o;
    o.x = *(uint32_t*)&a;
    o.y = *(uint32_t*)&b;
    out[i] = o;
}

// all 9 weight conversions fused: fp32 [K][N] -> bf16 [K][Npad] zero-padded
struct W2B {
    const float* src[9];
    __nv_bfloat16* dst[9];
    int N[9];
    int Npad[9];
    int cum[10];
};
__global__ void w2b_all_kernel(W2B b) {
    int i = blockIdx.x * blockDim.x + threadIdx.x;
    if (i >= b.cum[9]) return;
    int r = 0;
#pragma unroll
    for (int q = 0; q < 8; q++) if (i >= b.cum[q + 1]) r = q + 1;
    int local = i - b.cum[r];
    int Npad = b.Npad[r], N = b.N[r];
    int k = local / Npad, c = local - k * Npad;
    b.dst[r][local] = __float2bfloat16(c < N ? b.src[r][k * N + c] : 0.f);
}

// ---------------------------------------------------------------------------
// Gather-mean (bf16 in/out, fp32 accumulation). 64 threads per dst row.
// ---------------------------------------------------------------------------
__global__ void gather_mean_kernel(const __nv_bfloat16* __restrict__ feat,
                                   const int* __restrict__ rowptr,
                                   const int* __restrict__ csr_src,
                                   int num_dst,
                                   __nv_bfloat16* __restrict__ agg) {
    int group = blockIdx.x * 4 + (threadIdx.x >> 6);
    int lane  = threadIdx.x & 63;
    if (group >= num_dst) return;
    int beg = rowptr[group], end = rowptr[group + 1];
    int c4 = lane * 4;

    float s0 = 0.f, s1 = 0.f, s2 = 0.f, s3 = 0.f;
    int i = beg;
    for (; i + 1 < end; i += 2) {
        int sa = csr_src[i];
        int sb = csr_src[i + 1];
        uint2 ua = *(const uint2*)&feat[(size_t)sa * H_C + c4];
        uint2 ub = *(const uint2*)&feat[(size_t)sb * H_C + c4];
        float2 a0 = __bfloat1622float2(*(__nv_bfloat162*)&ua.x);
        float2 a1 = __bfloat1622float2(*(__nv_bfloat162*)&ua.y);
        float2 b0 = __bfloat1622float2(*(__nv_bfloat162*)&ub.x);
        float2 b1 = __bfloat1622float2(*(__nv_bfloat162*)&ub.y);
        s0 += a0.x + b0.x; s1 += a0.y + b0.y;
        s2 += a1.x + b1.x; s3 += a1.y + b1.y;
    }
    if (i < end) {
        int sa = csr_src[i];
        uint2 ua = *(const uint2*)&feat[(size_t)sa * H_C + c4];
        float2 a0 = __bfloat1622float2(*(__nv_bfloat162*)&ua.x);
        float2 a1 = __bfloat1622float2(*(__nv_bfloat162*)&ua.y);
        s0 += a0.x; s1 += a0.y; s2 += a1.x; s3 += a1.y;
    }
    float inv = (end > beg) ? 1.0f / (float)(end - beg) : 0.f;
    __nv_bfloat162 o0 = __floats2bfloat162_rn(s0 * inv, s1 * inv);
    __nv_bfloat162 o1 = __floats2bfloat162_rn(s2 * inv, s3 * inv);
    uint2 o;
    o.x = *(uint32_t*)&o0;
    o.y = *(uint32_t*)&o1;
    *(uint2*)&agg[(size_t)group * H_C + c4] = o;
}

// ---------------------------------------------------------------------------
// Pipelined fused multi-segment bf16 GEMM, BK=64, staged epilogue.
// ---------------------------------------------------------------------------
#define BM 128
#define BN 128
#define BK 64
#define PK 72    // A smem row stride (bf16): 144B, conflict-free LDSM
#define PN 136   // B smem row stride (bf16): 272B, conflict-free LDSM.trans
#define A_BYTES (BM * PK * 2)               // 18432
#define B_BYTES (BK * PN * 2)               // 17408
#define STAGE_BYTES (A_BYTES + B_BYTES)     // 35840
#define GEMM_SMEM (2 * STAGE_BYTES)         // 71680

struct GemmParams {
    const __nv_bfloat16* A[3];
    const __nv_bfloat16* B[3];
    int          K[3];
    int          nseg;
    const float* bias;
    void*        C;
    int          M, N, Npad;
};

__device__ __forceinline__ void cp16(uint32_t dst, const void* src, bool pred) {
    int sz = pred ? 16 : 0;
    asm volatile("cp.async.cg.shared.global [%0], [%1], 16, %2;"
                 :: "r"(dst), "l"(src), "r"(sz));
}

template<bool RELU, bool OUTBF16>
__global__ __launch_bounds__(256, 2)
void gemm_fused_kernel(GemmParams p) {
    extern __shared__ __align__(16) unsigned char smem_raw[];

    const int t    = threadIdx.x;
    const int lane = t & 31;
    const int w    = t >> 5;
    const int wm   = w & 1;
    const int wn   = w >> 1;
    const int g    = lane >> 2;
    const int tq   = lane & 3;
    const int row0 = blockIdx.y * BM;
    const int col0 = blockIdx.x * BN;
    const int M = p.M, N = p.N, Npad = p.Npad;
    const int nseg = p.nseg;

    const int kt0 = p.K[0] >> 6;
    const int kt1 = (nseg > 1) ? (p.K[1] >> 6) : 0;
    const int kt2 = (nseg > 2) ? (p.K[2] >> 6) : 0;
    const int total = kt0 + kt1 + kt2;

    const uint32_t smBase = (uint32_t)__cvta_generic_to_shared(smem_raw);

    const uint32_t aBase = smBase +
        (uint32_t)(((wm * 64 + (lane & 15)) * PK + ((lane >> 4) << 3)) << 1);
    const uint32_t bBase = smBase + A_BYTES +
        (uint32_t)(((lane & 15) * PN + wn * 32 + ((lane >> 4) << 3)) << 1);

    float acc[4][4][4];
#pragma unroll
    for (int i = 0; i < 4; i++)
#pragma unroll
        for (int j = 0; j < 4; j++)
#pragma unroll
            for (int v = 0; v < 4; v++) acc[i][j][v] = 0.f;

    // bounded segment walk; never spins
    auto issue = [&](int ti, int st) {
        int s = 0, rem = ti;
        if (rem >= kt0)           { rem -= kt0; s = 1; }
        if (s == 1 && rem >= kt1) { rem -= kt1; s = 2; }
        int k0 = rem * BK;
        const __nv_bfloat16* A = p.A[s];
        const __nv_bfloat16* B = p.B[s];
        int K = p.K[s];
        uint32_t sb = smBase + st * STAGE_BYTES;
        // A tile: 128 x 64 bf16 = 1024 16B chunks (full 128B rows)
#pragma unroll
        for (int it = 0; it < 4; it++) {
            int idx = t + it * 256;
            int r   = idx >> 3;
            int c8  = (idx & 7) * 8;
            int gr  = row0 + r;
            bool ok = (gr < M);
            int  sr = ok ? gr : 0;
            uint32_t dst = sb + (uint32_t)((r * PK + c8) << 1);
            cp16(dst, A + (size_t)sr * K + k0 + c8, ok);
        }
        // B tile: 64 x 128 bf16 = 1024 16B chunks
#pragma unroll
        for (int it = 0; it < 4; it++) {
            int idx = t + it * 256;
            int kr  = idx >> 4;
            int c8  = (idx & 15) * 8;
            int gc  = col0 + c8;
            bool ok = (gc < Npad);
            int  sc = ok ? gc : 0;
            uint32_t dst = sb + A_BYTES + (uint32_t)((kr * PN + c8) << 1);
            cp16(dst, B + (size_t)(k0 + kr) * Npad + sc, ok);
        }
        asm volatile("cp.async.commit_group;");
    };

    issue(0, 0);

    for (int ti = 0; ti < total; ti++) {
        if (ti + 1 < total) {
            issue(ti + 1, (ti + 1) & 1);
            asm volatile("cp.async.wait_group 1;");
        } else {
            asm volatile("cp.async.wait_group 0;");
        }
        __syncthreads();

        const uint32_t so = (uint32_t)((ti & 1) * STAGE_BYTES);
#pragma unroll
        for (int ks = 0; ks < 4; ks++) {
            const int ko = ks * 16;
            uint32_t a[4][4];
#pragma unroll
            for (int i = 0; i < 4; i++) {
                uint32_t addr = aBase + so + (uint32_t)(((i * 16) * PK + ko) << 1);
                asm volatile("ldmatrix.sync.aligned.m8n8.x4.shared.b16 {%0,%1,%2,%3}, [%4];"
                             : "=r"(a[i][0]), "=r"(a[i][1]), "=r"(a[i][2]), "=r"(a[i][3])
                             : "r"(addr));
            }
            uint32_t b[2][4];
#pragma unroll
            for (int jj = 0; jj < 2; jj++) {
                uint32_t addr = bBase + so + (uint32_t)((ko * PN + jj * 16) << 1);
                asm volatile("ldmatrix.sync.aligned.m8n8.x4.trans.shared.b16 {%0,%1,%2,%3}, [%4];"
                             : "=r"(b[jj][0]), "=r"(b[jj][1]), "=r"(b[jj][2]), "=r"(b[jj][3])
                             : "r"(addr));
            }
#pragma unroll
            for (int i = 0; i < 4; i++)
#pragma unroll
                for (int j = 0; j < 4; j++) {
                    uint32_t b0 = b[j >> 1][(j & 1) * 2];
                    uint32_t b1 = b[j >> 1][(j & 1) * 2 + 1];
                    asm volatile(
                        "mma.sync.aligned.m16n8k16.row.col.f32.bf16.bf16.f32 "
                        "{%0,%1,%2,%3}, {%4,%5,%6,%7}, {%8,%9}, {%0,%1,%2,%3};\n"
                        : "+f"(acc[i][j][0]), "+f"(acc[i][j][1]),
                          "+f"(acc[i][j][2]), "+f"(acc[i][j][3])
                        : "r"(a[i][0]), "r"(a[i][1]), "r"(a[i][2]), "r"(a[i][3]),
                          "r"(b0), "r"(b1));
                }
        }
        __syncthreads();
    }

    // ---- staged epilogue: coalesced global stores ----
    __syncthreads();   // smem free for reuse
    if (OUTBF16) {
        __nv_bfloat16* cs = (__nv_bfloat16*)smem_raw;   // [128][136]
        __nv_bfloat16* Cb = (__nv_bfloat16*)p.C;
#pragma unroll
        for (int i = 0; i < 4; i++) {
            int r0l = wm * 64 + i * 16 + g;
#pragma unroll
            for (int j = 0; j < 4; j++) {
                int cl = wn * 32 + j * 8 + tq * 2;
                float bv0 = p.bias[col0 + cl];
                float bv1 = p.bias[col0 + cl + 1];
                float x0 = acc[i][j][0] + bv0, x1 = acc[i][j][1] + bv1;
                float y0 = acc[i][j][2] + bv0, y1 = acc[i][j][3] + bv1;
                if (RELU) {
                    x0 = fmaxf(x0, 0.f); x1 = fmaxf(x1, 0.f);
                    y0 = fmaxf(y0, 0.f); y1 = fmaxf(y1, 0.f);
                }
                *(__nv_bfloat162*)&cs[r0l * 136 + cl]       = __floats2bfloat162_rn(x0, x1);
                *(__nv_bfloat162*)&cs[(r0l + 8) * 136 + cl] = __floats2bfloat162_rn(y0, y1);
            }
        }
        __syncthreads();
#pragma unroll
        for (int it = 0; it < 8; it++) {
            int idx = t + it * 256;
            int r   = idx >> 4;
            int c8  = (idx & 15) * 8;
            int gr  = row0 + r;
            int gc  = col0 + c8;
            if (gr < M) {
                if (gc + 8 <= N) {
                    *(uint4*)&Cb[(size_t)gr * N + gc] = *(uint4*)&cs[r * 136 + c8];
                } else {
                    for (int e = 0; e < 8; e++)
                        if (gc + e < N) Cb[(size_t)gr * N + gc + e] = cs[r * 136 + c8 + e];
                }
            }
        }
    } else {
        float* cs = (float*)smem_raw;   // [64][132] per half
        float* Cf = (float*)p.C;
#pragma unroll
        for (int half = 0; half < 2; half++) {
            __syncthreads();
            if (wm == half) {
#pragma unroll
                for (int i = 0; i < 4; i++) {
                    int r0l = i * 16 + g;
#pragma unroll
                    for (int j = 0; j < 4; j++) {
                        int cl = wn * 32 + j * 8 + tq * 2;
                        float bv0 = p.bias[col0 + cl];
                        float bv1 = p.bias[col0 + cl + 1];
                        cs[r0l * 132 + cl]           = acc[i][j][0] + bv0;
                        cs[r0l * 132 + cl + 1]       = acc[i][j][1] + bv1;
                        cs[(r0l + 8) * 132 + cl]     = acc[i][j][2] + bv0;
                        cs[(r0l + 8) * 132 + cl + 1] = acc[i][j][3] + bv1;
                    }
                }
            }
            __syncthreads();
            // coalesced scalar copy (N=349 stride is not 16B-aligned)
#pragma unroll
            for (int it = 0; it < 32; it++) {
                int idx = t + it * 256;
                int r   = idx >> 7;
                int c   = idx & 127;
                int gr  = row0 + half * 64 + r;
                int gc  = col0 + c;
                if (gr < M && gc < N)
                    Cf[(size_t)gr * N + gc] = cs[r * 132 + c];
            }
        }
    }
}

// ---------------------------------------------------------------------------
__inline__ __device__ float warpMax(float v) {
#pragma unroll
    for (int o = 16; o; o >>= 1) v = fmaxf(v, __shfl_xor_sync(0xFFFFFFFFu, v, o));
    return v;
}
__inline__ __device__ float warpSum(float v) {
#pragma unroll
    for (int o = 16; o; o >>= 1) v += __shfl_xor_sync(0xFFFFFFFFu, v, o);
    return v;
}

__global__ void log_softmax_kernel(float* __restrict__ x, int N) {
    float* r = x + (size_t)blockIdx.x * N;
    int t = threadIdx.x;

    float m = -1e30f;
    for (int i = t; i < N; i += 128) m = fmaxf(m, r[i]);
    m = warpMax(m);
    __shared__ float shm[4];
    if ((t & 31) == 0) shm[t >> 5] = m;
    __syncthreads();
    m = fmaxf(fmaxf(shm[0], shm[1]), fmaxf(shm[2], shm[3]));

    float s = 0.f;
    for (int i = t; i < N; i += 128) s += expf(r[i] - m);
    s = warpSum(s);
    __shared__ float shs[4];
    if ((t & 31) == 0) shs[t >> 5] = s;
    __syncthreads();
    s = shs[0] + shs[1] + shs[2] + shs[3];

    float lse = m + logf(s);
    for (int i = t; i < N; i += 128) r[i] = r[i] - lse;
}

// ---------------------------------------------------------------------------
static void run_gemm_fused(bool relu, bool outbf16, const GemmParams& p) {
    dim3 grid((p.N + BN - 1) / BN, (p.M + BM - 1) / BM);
    if (relu) {
        // only the bf16-out+relu variant is used
        gemm_fused_kernel<true, true><<<grid, 256, GEMM_SMEM>>>(p);
    } else {
        if (outbf16) gemm_fused_kernel<false, true ><<<grid, 256, GEMM_SMEM>>>(p);
        else         gemm_fused_kernel<false, false><<<grid, 256, GEMM_SMEM>>>(p);
    }
}

static void run_scans(const int* cnt, int n, int* bsum, int* rowptr, int* nextp) {
    int nb = (n + SCB - 1) / SCB;
    scan1_kernel<<<nb, SCB>>>(cnt, n, bsum);
    scan2_kernel<<<1, SCB>>>(bsum, nb);
    scan3_kernel<<<nb, SCB>>>(cnt, n, bsum, rowptr, nextp);
}

static void run_gather(const __nv_bfloat16* feat, const int* rowptr, const int* csr_src,
                       int num_dst, __nv_bfloat16* agg) {
    gather_mean_kernel<<<(num_dst + 3) / 4, 256>>>(feat, rowptr, csr_src, num_dst, agg);
}

extern "C" void kernel_launch(void* const* d_in, const int* in_sizes, int n_in,
                              void* d_out, int out_size) {
    const float* x_paper          = (const float*)d_in[0];
    const float* emb_author       = (const float*)d_in[1];
    const float* lin_paper_w      = (const float*)d_in[2];
    const float* lin_paper_b      = (const float*)d_in[3];
    const float* c0_root_paper_w  = (const float*)d_in[4];
    const float* c0_root_paper_b  = (const float*)d_in[5];
    const float* c0_root_author_w = (const float*)d_in[6];
    const float* c0_root_author_b = (const float*)d_in[7];
    const float* c0_rel_writes_w  = (const float*)d_in[8];
    const float* c0_rel_cites_w   = (const float*)d_in[9];
    const float* c0_rel_revw_w    = (const float*)d_in[10];
    const float* c1_root_w        = (const float*)d_in[11];
    const float* c1_root_b        = (const float*)d_in[12];
    const float* c1_rel_writes_w  = (const float*)d_in[13];
    const float* c1_rel_cites_w   = (const float*)d_in[14];
    const int*   writes_src       = (const int*)d_in[15];
    const int*   writes_dst       = (const int*)d_in[16];
    const int*   cites_src        = (const int*)d_in[17];
    const int*   cites_dst        = (const int*)d_in[18];
    const int*   revw_src         = (const int*)d_in[19];
    const int*   revw_dst         = (const int*)d_in[20];

    const int E_W = in_sizes[15];
    const int E_C = in_sizes[17];
    float* out = (float*)d_out;

    __nv_bfloat16 *hp, *outp, *outa, *aggA, *aggB, *emba, *xb;
    __nv_bfloat16 *wlin, *w0rp, *w0ra, *w0w, *w0c, *w0r, *w1rt, *w1w, *w1c;
    int *cntW, *cntC, *cntR, *rpW, *rpC, *rpR, *nxW, *nxC, *nxR, *csW, *csC, *csR, *bsum;
    cudaGetSymbolAddress((void**)&hp,   g_hp);
    cudaGetSymbolAddress((void**)&outp, g_outp);
    cudaGetSymbolAddress((void**)&outa, g_outa);
    cudaGetSymbolAddress((void**)&aggA, g_aggA);
    cudaGetSymbolAddress((void**)&aggB, g_aggB);
    cudaGetSymbolAddress((void**)&emba, g_emba);
    cudaGetSymbolAddress((void**)&xb,   g_xb);
    cudaGetSymbolAddress((void**)&wlin, g_wlin);
    cudaGetSymbolAddress((void**)&w0rp, g_w0rp);
    cudaGetSymbolAddress((void**)&w0ra, g_w0ra);
    cudaGetSymbolAddress((void**)&w0w,  g_w0w);
    cudaGetSymbolAddress((void**)&w0c,  g_w0c);
    cudaGetSymbolAddress((void**)&w0r,  g_w0r);
    cudaGetSymbolAddress((void**)&w1rt, g_w1rt);
    cudaGetSymbolAddress((void**)&w1w,  g_w1w);
    cudaGetSymbolAddress((void**)&w1c,  g_w1c);
    cudaGetSymbolAddress((void**)&cntW, g_cntW);
    cudaGetSymbolAddress((void**)&cntC, g_cntC);
    cudaGetSymbolAddress((void**)&cntR, g_cntR);
    cudaGetSymbolAddress((void**)&rpW,  g_rpW);
    cudaGetSymbolAddress((void**)&rpC,  g_rpC);
    cudaGetSymbolAddress((void**)&rpR,  g_rpR);
    cudaGetSymbolAddress((void**)&nxW,  g_nxW);
    cudaGetSymbolAddress((void**)&nxC,  g_nxC);
    cudaGetSymbolAddress((void**)&nxR,  g_nxR);
    cudaGetSymbolAddress((void**)&csW,  g_csW);
    cudaGetSymbolAddress((void**)&csC,  g_csC);
    cudaGetSymbolAddress((void**)&csR,  g_csR);
    cudaGetSymbolAddress((void**)&bsum, g_bsum);

    // opt-in large dynamic smem (idempotent)
    cudaFuncSetAttribute(gemm_fused_kernel<false, true >, cudaFuncAttributeMaxDynamicSharedMemorySize, GEMM_SMEM);
    cudaFuncSetAttribute(gemm_fused_kernel<true,  true >, cudaFuncAttributeMaxDynamicSharedMemorySize, GEMM_SMEM);
    cudaFuncSetAttribute(gemm_fused_kernel<false, false>, cudaFuncAttributeMaxDynamicSharedMemorySize, GEMM_SMEM);

    // --- launches 0-1: feature conversions ---
    f2b_kernel<<<((A_N * H_C / 4) + 255) / 256, 256>>>(
        (const float4*)emb_author, (uint2*)emba, A_N * H_C / 4);
    f2b_kernel<<<((P_N * IN_C / 4) + 255) / 256, 256>>>(
        (const float4*)x_paper, (uint2*)xb, P_N * IN_C / 4);

    // --- launch 2: all weight conversions ---
    {
        W2B b = {};
        const float* srcs[9] = {lin_paper_w, c0_root_paper_w, c0_root_author_w,
                                c0_rel_writes_w, c0_rel_cites_w, c0_rel_revw_w,
                                c1_root_w, c1_rel_writes_w, c1_rel_cites_w};
        __nv_bfloat16* dsts[9] = {wlin, w0rp, w0ra, w0w, w0c, w0r, w1rt, w1w, w1c};
        int Ns[9]    = {H_C, H_C, H_C, H_C, H_C, H_C, OUT_C, OUT_C, OUT_C};
        int Npads[9] = {H_C, H_C, H_C, H_C, H_C, H_C, 352, 352, 352};
        int Ks[9]    = {IN_C, H_C, H_C, H_C, H_C, H_C, H_C, H_C, H_C};
        int cum = 0;
        for (int q = 0; q < 9; q++) {
            b.src[q] = srcs[q]; b.dst[q] = dsts[q];
            b.N[q] = Ns[q]; b.Npad[q] = Npads[q];
            b.cum[q] = cum; cum += Ks[q] * Npads[q];
        }
        b.cum[9] = cum;
        w2b_all_kernel<<<(cum + 255) / 256, 256>>>(b);
    }

    // --- launch 3: zero count arrays; 4: count writes ---
    {
        int na4 = P_N / 4, nb4 = P_N / 4, nc4 = A_N / 4;
        fill3_kernel<<<(na4 + nb4 + nc4 + 255) / 256, 256>>>(
            (int4*)cntW, na4, (int4*)cntC, nb4, (int4*)cntR, nc4);
    }
    count_int_kernel<<<(E_W + 255) / 256, 256>>>(writes_dst, E_W, cntW);

    // --- launch 5: GEMM1 (hp = x@Wlin + b)  [profiled by ncu -s 5 -c 1] ---
    {
        GemmParams p = {};
        p.A[0] = xb; p.B[0] = wlin; p.K[0] = IN_C;
        p.nseg = 1; p.bias = lin_paper_b; p.C = hp; p.M = P_N; p.N = H_C; p.Npad = H_C;
        run_gemm_fused(false, true, p);
    }

    // --- remaining CSR builds ---
    count_int_kernel<<<(E_C + 255) / 256, 256>>>(cites_dst, E_C, cntC);
    count_int_kernel<<<(E_W + 255) / 256, 256>>>(revw_dst,  E_W, cntR);
    run_scans(cntW, P_N, bsum, rpW, nxW);
    build_csr_kernel<<<(E_W + 255) / 256, 256>>>(writes_src, writes_dst, E_W, nxW, csW);
    run_scans(cntC, P_N, bsum, rpC, nxC);
    build_csr_kernel<<<(E_C + 255) / 256, 256>>>(cites_src, cites_dst, E_C, nxC, csC);
    run_scans(cntR, A_N, bsum, rpR, nxR);
    build_csr_kernel<<<(E_W + 255) / 256, 256>>>(revw_src, revw_dst, E_W, nxR, csR);

    // --- layer-0 gathers + paper GEMM ---
    run_gather(emba, rpW, csW, P_N, aggA);
    run_gather(hp,   rpC, csC, P_N, aggB);
    {
        GemmParams p = {};
        p.A[0] = hp;   p.B[0] = w0rp; p.K[0] = H_C;
        p.A[1] = aggA; p.B[1] = w0w;  p.K[1] = H_C;
        p.A[2] = aggB; p.B[2] = w0c;  p.K[2] = H_C;
        p.nseg = 3; p.bias = c0_root_paper_b; p.C = outp; p.M = P_N; p.N = H_C; p.Npad = H_C;
        run_gemm_fused(true, true, p);
    }

    // --- author side ---
    run_gather(hp, rpR, csR, A_N, aggA);
    {
        GemmParams p = {};
        p.A[0] = emba; p.B[0] = w0ra; p.K[0] = H_C;
        p.A[1] = aggA; p.B[1] = w0r;  p.K[1] = H_C;
        p.nseg = 2; p.bias = c0_root_author_b; p.C = outa; p.M = A_N; p.N = H_C; p.Npad = H_C;
        run_gemm_fused(true, true, p);
    }

    // --- layer-1 gathers + output GEMM ---
    run_gather(outa, rpW, csW, P_N, aggA);
    run_gather(outp, rpC, csC, P_N, aggB);
    {
        GemmParams p = {};
        p.A[0] = outp; p.B[0] = w1rt; p.K[0] = H_C;
        p.A[1] = aggA; p.B[1] = w1w;  p.K[1] = H_C;
        p.A[2] = aggB; p.B[2] = w1c;  p.K[2] = H_C;
        p.nseg = 3; p.bias = c1_root_b; p.C = out; p.M = P_N; p.N = OUT_C; p.Npad = 352;
        run_gemm_fused(false, false, p);
    }

    // --- log_softmax ---
    log_softmax_kernel<<<P_N, 128>>>(out, OUT_C);
}

// round 9
// speedup vs baseline: 8.8355x; 1.0575x over previous
#include <cuda_runtime.h>
#include <cuda_bf16.h>
#include <cstdint>

// ---------------------------------------------------------------------------
// RGCN forward. CSR gather-mean (warp-per-row, bf16), pipelined bf16 HMMA
// GEMMs: BK=64, 3-stage cp.async, ldmatrix frags, smem-staged epilogues.
// P=100000, A=50000, IN=128, H=256, OUT=349
// ---------------------------------------------------------------------------

#define P_N   100000
#define A_N   50000
#define IN_C  128
#define H_C   256
#define OUT_C 349
#define EW_MAX 600000
#define EC_MAX 1000000

// bf16 feature buffers
__device__ __nv_bfloat16 g_hp  [(size_t)P_N * H_C];
__device__ __nv_bfloat16 g_outp[(size_t)P_N * H_C];
__device__ __nv_bfloat16 g_outa[(size_t)A_N * H_C];
__device__ __nv_bfloat16 g_aggA[(size_t)P_N * H_C];
__device__ __nv_bfloat16 g_aggB[(size_t)P_N * H_C];
__device__ __nv_bfloat16 g_emba[(size_t)A_N * H_C];
__device__ __nv_bfloat16 g_xb  [(size_t)P_N * IN_C];

// bf16 weights (padded to Npad columns)
__device__ __nv_bfloat16 g_wlin [IN_C * H_C];
__device__ __nv_bfloat16 g_w0rp [H_C * H_C];
__device__ __nv_bfloat16 g_w0ra [H_C * H_C];
__device__ __nv_bfloat16 g_w0w  [H_C * H_C];
__device__ __nv_bfloat16 g_w0c  [H_C * H_C];
__device__ __nv_bfloat16 g_w0r  [H_C * H_C];
__device__ __nv_bfloat16 g_w1rt [H_C * 352];
__device__ __nv_bfloat16 g_w1w  [H_C * 352];
__device__ __nv_bfloat16 g_w1c  [H_C * 352];

// CSR scratch
__device__ int g_cntW[P_N], g_cntC[P_N], g_cntR[A_N];
__device__ int g_rpW[P_N + 1], g_rpC[P_N + 1], g_rpR[A_N + 1];
__device__ int g_nxW[P_N], g_nxC[P_N], g_nxR[A_N];
__device__ int g_csW[EW_MAX], g_csC[EC_MAX], g_csR[EW_MAX];
__device__ int g_bsum[1024];

// ---------------------------------------------------------------------------
__global__ void fill3_kernel(int4* a, int na4, int4* b, int nb4, int4* c, int nc4) {
    int i = blockIdx.x * blockDim.x + threadIdx.x;
    int4 z = make_int4(0, 0, 0, 0);
    if (i < na4) a[i] = z;
    else if (i < na4 + nb4) b[i - na4] = z;
    else if (i < na4 + nb4 + nc4) c[i - na4 - nb4] = z;
}

__global__ void count_int_kernel(const int* __restrict__ dst, int E, int* __restrict__ cnt) {
    int i = blockIdx.x * blockDim.x + threadIdx.x;
    if (i < E) atomicAdd(&cnt[dst[i]], 1);
}

// ---------------------------------------------------------------------------
#define SCB 1024

__global__ void scan1_kernel(const int* __restrict__ cnt, int n, int* __restrict__ bsum) {
    __shared__ int sh[SCB];
    int tid = threadIdx.x;
    int i = blockIdx.x * SCB + tid;
    sh[tid] = (i < n) ? cnt[i] : 0;
    __syncthreads();
    for (int off = SCB / 2; off; off >>= 1) {
        if (tid < off) sh[tid] += sh[tid + off];
        __syncthreads();
    }
    if (!tid) bsum[blockIdx.x] = sh[0];
}

__global__ void scan2_kernel(int* __restrict__ bsum, int nb) {
    __shared__ int sh[SCB];
    int tid = threadIdx.x;
    int v = (tid < nb) ? bsum[tid] : 0;
    sh[tid] = v;
    __syncthreads();
    for (int off = 1; off < SCB; off <<= 1) {
        int a = (tid >= off) ? sh[tid - off] : 0;
        __syncthreads();
        sh[tid] += a;
        __syncthreads();
    }
    if (tid < nb) bsum[tid] = sh[tid] - v;
}

__global__ void scan3_kernel(const int* __restrict__ cnt, int n, const int* __restrict__ bsum,
                             int* __restrict__ rowptr, int* __restrict__ nextp) {
    __shared__ int sh[SCB];
    int tid = threadIdx.x;
    int i = blockIdx.x * SCB + tid;
    int v = (i < n) ? cnt[i] : 0;
    sh[tid] = v;
    __syncthreads();
    for (int off = 1; off < SCB; off <<= 1) {
        int a = (tid >= off) ? sh[tid - off] : 0;
        __syncthreads();
        sh[tid] += a;
        __syncthreads();
    }
    int excl = sh[tid] - v + bsum[blockIdx.x];
    if (i < n) { rowptr[i] = excl; nextp[i] = excl; }
    if (i == n - 1) rowptr[n] = excl + v;
}

__global__ void build_csr_kernel(const int* __restrict__ src, const int* __restrict__ dst,
                                 int E, int* __restrict__ nextp, int* __restrict__ csr_src) {
    int i = blockIdx.x * blockDim.x + threadIdx.x;
    if (i < E) {
        int p = atomicAdd(&nextp[dst[i]], 1);
        csr_src[p] = src[i];
    }
}

// ---------------------------------------------------------------------------
__global__ void f2b_kernel(const float4* __restrict__ in, uint2* __restrict__ out, int n4) {
    int i = blockIdx.x * blockDim.x + threadIdx.x;
    if (i >= n4) return;
    float4 v = in[i];
    __nv_bfloat162 a = __floats2bfloat162_rn(v.x, v.y);
    __nv_bfloat162 b = __floats2bfloat162_rn(v.z, v.w);
    uint2 o;
    o.x = *(uint32_t*)&a;
    o.y = *(uint32_t*)&b;
    out[i] = o;
}

// all 9 weight conversions fused: fp32 [K][N] -> bf16 [K][Npad] zero-padded
struct W2B {
    const float* src[9];
    __nv_bfloat16* dst[9];
    int N[9];
    int Npad[9];
    int cum[10];
};
__global__ void w2b_all_kernel(W2B b) {
    int i = blockIdx.x * blockDim.x + threadIdx.x;
    if (i >= b.cum[9]) return;
    int r = 0;
#pragma unroll
    for (int q = 0; q < 8; q++) if (i >= b.cum[q + 1]) r = q + 1;
    int local = i - b.cum[r];
    int Npad = b.Npad[r], N = b.N[r];
    int k = local / Npad, c = local - k * Npad;
    b.dst[r][local] = __float2bfloat16(c < N ? b.src[r][k * N + c] : 0.f);
}

// ---------------------------------------------------------------------------
// Gather-mean (bf16 in/out, fp32 accumulation). One warp per dst row;
// each lane owns 8 channels (one uint4 = 16B per neighbor).
// ---------------------------------------------------------------------------
__device__ __forceinline__ void acc8(float* s, uint4 u) {
    float2 f0 = __bfloat1622float2(*(__nv_bfloat162*)&u.x);
    float2 f1 = __bfloat1622float2(*(__nv_bfloat162*)&u.y);
    float2 f2 = __bfloat1622float2(*(__nv_bfloat162*)&u.z);
    float2 f3 = __bfloat1622float2(*(__nv_bfloat162*)&u.w);
    s[0] += f0.x; s[1] += f0.y; s[2] += f1.x; s[3] += f1.y;
    s[4] += f2.x; s[5] += f2.y; s[6] += f3.x; s[7] += f3.y;
}

__global__ void gather_mean_kernel(const __nv_bfloat16* __restrict__ feat,
                                   const int* __restrict__ rowptr,
                                   const int* __restrict__ csr_src,
                                   int num_dst,
                                   __nv_bfloat16* __restrict__ agg) {
    int group = blockIdx.x * 8 + (threadIdx.x >> 5);
    int lane  = threadIdx.x & 31;
    if (group >= num_dst) return;
    int beg = rowptr[group], end = rowptr[group + 1];
    int c8 = lane * 8;

    float s[8] = {0.f, 0.f, 0.f, 0.f, 0.f, 0.f, 0.f, 0.f};
    int i = beg;
    for (; i + 1 < end; i += 2) {
        int sa = csr_src[i];
        int sb = csr_src[i + 1];
        uint4 ua = *(const uint4*)&feat[(size_t)sa * H_C + c8];
        uint4 ub = *(const uint4*)&feat[(size_t)sb * H_C + c8];
        acc8(s, ua);
        acc8(s, ub);
    }
    if (i < end) {
        int sa = csr_src[i];
        uint4 ua = *(const uint4*)&feat[(size_t)sa * H_C + c8];
        acc8(s, ua);
    }
    float inv = (end > beg) ? 1.0f / (float)(end - beg) : 0.f;
    __nv_bfloat162 o0 = __floats2bfloat162_rn(s[0] * inv, s[1] * inv);
    __nv_bfloat162 o1 = __floats2bfloat162_rn(s[2] * inv, s[3] * inv);
    __nv_bfloat162 o2 = __floats2bfloat162_rn(s[4] * inv, s[5] * inv);
    __nv_bfloat162 o3 = __floats2bfloat162_rn(s[6] * inv, s[7] * inv);
    uint4 o;
    o.x = *(uint32_t*)&o0; o.y = *(uint32_t*)&o1;
    o.z = *(uint32_t*)&o2; o.w = *(uint32_t*)&o3;
    *(uint4*)&agg[(size_t)group * H_C + c8] = o;
}

// ---------------------------------------------------------------------------
// Pipelined fused multi-segment bf16 GEMM, BK=64, 3-stage, staged epilogue.
// ---------------------------------------------------------------------------
#define BM 128
#define BN 128
#define BK 64
#define PK 72    // A smem row stride (bf16): 144B, conflict-free LDSM
#define PN 136   // B smem row stride (bf16): 272B, conflict-free LDSM.trans
#define A_BYTES (BM * PK * 2)               // 18432
#define B_BYTES (BK * PN * 2)               // 17408
#define STAGE_BYTES (A_BYTES + B_BYTES)     // 35840
#define NSTAGE 3
#define GEMM_SMEM (NSTAGE * STAGE_BYTES)    // 107520

struct GemmParams {
    const __nv_bfloat16* A[3];
    const __nv_bfloat16* B[3];
    int          K[3];
    int          nseg;
    const float* bias;
    void*        C;
    int          M, N, Npad;
};

__device__ __forceinline__ void cp16(uint32_t dst, const void* src, bool pred) {
    int sz = pred ? 16 : 0;
    asm volatile("cp.async.cg.shared.global [%0], [%1], 16, %2;"
                 :: "r"(dst), "l"(src), "r"(sz));
}

template<bool RELU, bool OUTBF16>
__global__ __launch_bounds__(256, 2)
void gemm_fused_kernel(GemmParams p) {
    extern __shared__ __align__(16) unsigned char smem_raw[];

    const int t    = threadIdx.x;
    const int lane = t & 31;
    const int w    = t >> 5;
    const int wm   = w & 1;
    const int wn   = w >> 1;
    const int g    = lane >> 2;
    const int tq   = lane & 3;
    const int row0 = blockIdx.y * BM;
    const int col0 = blockIdx.x * BN;
    const int M = p.M, N = p.N, Npad = p.Npad;
    const int nseg = p.nseg;

    const int kt0 = p.K[0] >> 6;
    const int kt1 = (nseg > 1) ? (p.K[1] >> 6) : 0;
    const int kt2 = (nseg > 2) ? (p.K[2] >> 6) : 0;
    const int total = kt0 + kt1 + kt2;

    const uint32_t smBase = (uint32_t)__cvta_generic_to_shared(smem_raw);

    const uint32_t aBase = smBase +
        (uint32_t)(((wm * 64 + (lane & 15)) * PK + ((lane >> 4) << 3)) << 1);
    const uint32_t bBase = smBase + A_BYTES +
        (uint32_t)(((lane & 15) * PN + wn * 32 + ((lane >> 4) << 3)) << 1);

    float acc[4][4][4];
#pragma unroll
    for (int i = 0; i < 4; i++)
#pragma unroll
        for (int j = 0; j < 4; j++)
#pragma unroll
            for (int v = 0; v < 4; v++) acc[i][j][v] = 0.f;

    // bounded segment walk; never spins
    auto issue = [&](int ti) {
        int s = 0, rem = ti;
        if (rem >= kt0)           { rem -= kt0; s = 1; }
        if (s == 1 && rem >= kt1) { rem -= kt1; s = 2; }
        int k0 = rem * BK;
        const __nv_bfloat16* A = p.A[s];
        const __nv_bfloat16* B = p.B[s];
        int K = p.K[s];
        uint32_t sb = smBase + (uint32_t)((ti % NSTAGE) * STAGE_BYTES);
        // A tile: 128 x 64 bf16 = 1024 16B chunks (full 128B rows)
#pragma unroll
        for (int it = 0; it < 4; it++) {
            int idx = t + it * 256;
            int r   = idx >> 3;
            int c8  = (idx & 7) * 8;
            int gr  = row0 + r;
            bool ok = (gr < M);
            int  sr = ok ? gr : 0;
            uint32_t dst = sb + (uint32_t)((r * PK + c8) << 1);
            cp16(dst, A + (size_t)sr * K + k0 + c8, ok);
        }
        // B tile: 64 x 128 bf16 = 1024 16B chunks
#pragma unroll
        for (int it = 0; it < 4; it++) {
            int idx = t + it * 256;
            int kr  = idx >> 4;
            int c8  = (idx & 15) * 8;
            int gc  = col0 + c8;
            bool ok = (gc < Npad);
            int  sc = ok ? gc : 0;
            uint32_t dst = sb + A_BYTES + (uint32_t)((kr * PN + c8) << 1);
            cp16(dst, B + (size_t)(k0 + kr) * Npad + sc, ok);
        }
        asm volatile("cp.async.commit_group;");
    };

    issue(0);
    if (total > 1) issue(1);

    for (int ti = 0; ti < total; ti++) {
        if (ti + 2 < total) {
            issue(ti + 2);
            asm volatile("cp.async.wait_group 2;");
        } else if (ti + 1 < total) {
            asm volatile("cp.async.wait_group 1;");
        } else {
            asm volatile("cp.async.wait_group 0;");
        }
        __syncthreads();

        const uint32_t so = (uint32_t)((ti % NSTAGE) * STAGE_BYTES);
#pragma unroll
        for (int ks = 0; ks < 4; ks++) {
            const int ko = ks * 16;
            uint32_t a[4][4];
#pragma unroll
            for (int i = 0; i < 4; i++) {
                uint32_t addr = aBase + so + (uint32_t)(((i * 16) * PK + ko) << 1);
                asm volatile("ldmatrix.sync.aligned.m8n8.x4.shared.b16 {%0,%1,%2,%3}, [%4];"
                             : "=r"(a[i][0]), "=r"(a[i][1]), "=r"(a[i][2]), "=r"(a[i][3])
                             : "r"(addr));
            }
            uint32_t b[2][4];
#pragma unroll
            for (int jj = 0; jj < 2; jj++) {
                uint32_t addr = bBase + so + (uint32_t)((ko * PN + jj * 16) << 1);
                asm volatile("ldmatrix.sync.aligned.m8n8.x4.trans.shared.b16 {%0,%1,%2,%3}, [%4];"
                             : "=r"(b[jj][0]), "=r"(b[jj][1]), "=r"(b[jj][2]), "=r"(b[jj][3])
                             : "r"(addr));
            }
#pragma unroll
            for (int i = 0; i < 4; i++)
#pragma unroll
                for (int j = 0; j < 4; j++) {
                    uint32_t b0 = b[j >> 1][(j & 1) * 2];
                    uint32_t b1 = b[j >> 1][(j & 1) * 2 + 1];
                    asm volatile(
                        "mma.sync.aligned.m16n8k16.row.col.f32.bf16.bf16.f32 "
                        "{%0,%1,%2,%3}, {%4,%5,%6,%7}, {%8,%9}, {%0,%1,%2,%3};\n"
                        : "+f"(acc[i][j][0]), "+f"(acc[i][j][1]),
                          "+f"(acc[i][j][2]), "+f"(acc[i][j][3])
                        : "r"(a[i][0]), "r"(a[i][1]), "r"(a[i][2]), "r"(a[i][3]),
                          "r"(b0), "r"(b1));
                }
        }
        __syncthreads();
    }

    // ---- staged epilogue: coalesced global stores ----
    __syncthreads();
    if (OUTBF16) {
        __nv_bfloat16* cs = (__nv_bfloat16*)smem_raw;   // [128][136]
        __nv_bfloat16* Cb = (__nv_bfloat16*)p.C;
#pragma unroll
        for (int i = 0; i < 4; i++) {
            int r0l = wm * 64 + i * 16 + g;
#pragma unroll
            for (int j = 0; j < 4; j++) {
                int cl = wn * 32 + j * 8 + tq * 2;
                float bv0 = p.bias[col0 + cl];
                float bv1 = p.bias[col0 + cl + 1];
                float x0 = acc[i][j][0] + bv0, x1 = acc[i][j][1] + bv1;
                float y0 = acc[i][j][2] + bv0, y1 = acc[i][j][3] + bv1;
                if (RELU) {
                    x0 = fmaxf(x0, 0.f); x1 = fmaxf(x1, 0.f);
                    y0 = fmaxf(y0, 0.f); y1 = fmaxf(y1, 0.f);
                }
                *(__nv_bfloat162*)&cs[r0l * 136 + cl]       = __floats2bfloat162_rn(x0, x1);
                *(__nv_bfloat162*)&cs[(r0l + 8) * 136 + cl] = __floats2bfloat162_rn(y0, y1);
            }
        }
        __syncthreads();
#pragma unroll
        for (int it = 0; it < 8; it++) {
            int idx = t + it * 256;
            int r   = idx >> 4;
            int c8  = (idx & 15) * 8;
            int gr  = row0 + r;
            int gc  = col0 + c8;
            if (gr < M) {
                if (gc + 8 <= N) {
                    *(uint4*)&Cb[(size_t)gr * N + gc] = *(uint4*)&cs[r * 136 + c8];
                } else {
                    for (int e = 0; e < 8; e++)
                        if (gc + e < N) Cb[(size_t)gr * N + gc + e] = cs[r * 136 + c8 + e];
                }
            }
        }
    } else {
        float* cs = (float*)smem_raw;   // [64][132] per half
        float* Cf = (float*)p.C;
#pragma unroll
        for (int half = 0; half < 2; half++) {
            __syncthreads();
            if (wm == half) {
#pragma unroll
                for (int i = 0; i < 4; i++) {
                    int r0l = i * 16 + g;
#pragma unroll
                    for (int j = 0; j < 4; j++) {
                        int cl = wn * 32 + j * 8 + tq * 2;
                        float bv0 = p.bias[col0 + cl];
                        float bv1 = p.bias[col0 + cl + 1];
                        cs[r0l * 132 + cl]           = acc[i][j][0] + bv0;
                        cs[r0l * 132 + cl + 1]       = acc[i][j][1] + bv1;
                        cs[(r0l + 8) * 132 + cl]     = acc[i][j][2] + bv0;
                        cs[(r0l + 8) * 132 + cl + 1] = acc[i][j][3] + bv1;
                    }
                }
            }
            __syncthreads();
#pragma unroll
            for (int it = 0; it < 32; it++) {
                int idx = t + it * 256;
                int r   = idx >> 7;
                int c   = idx & 127;
                int gr  = row0 + half * 64 + r;
                int gc  = col0 + c;
                if (gr < M && gc < N)
                    Cf[(size_t)gr * N + gc] = cs[r * 132 + c];
            }
        }
    }
}

// ---------------------------------------------------------------------------
__inline__ __device__ float warpMax(float v) {
#pragma unroll
    for (int o = 16; o; o >>= 1) v = fmaxf(v, __shfl_xor_sync(0xFFFFFFFFu, v, o));
    return v;
}
__inline__ __device__ float warpSum(float v) {
#pragma unroll
    for (int o = 16; o; o >>= 1) v += __shfl_xor_sync(0xFFFFFFFFu, v, o);
    return v;
}

__global__ void log_softmax_kernel(float* __restrict__ x, int N) {
    float* r = x + (size_t)blockIdx.x * N;
    int t = threadIdx.x;

    float m = -1e30f;
    for (int i = t; i < N; i += 128) m = fmaxf(m, r[i]);
    m = warpMax(m);
    __shared__ float shm[4];
    if ((t & 31) == 0) shm[t >> 5] = m;
    __syncthreads();
    m = fmaxf(fmaxf(shm[0], shm[1]), fmaxf(shm[2], shm[3]));

    float s = 0.f;
    for (int i = t; i < N; i += 128) s += expf(r[i] - m);
    s = warpSum(s);
    __shared__ float shs[4];
    if ((t & 31) == 0) shs[t >> 5] = s;
    __syncthreads();
    s = shs[0] + shs[1] + shs[2] + shs[3];

    float lse = m + logf(s);
    for (int i = t; i < N; i += 128) r[i] = r[i] - lse;
}

// ---------------------------------------------------------------------------
static void run_gemm_fused(bool relu, bool outbf16, const GemmParams& p) {
    dim3 grid((p.N + BN - 1) / BN, (p.M + BM - 1) / BM);
    if (relu) {
        gemm_fused_kernel<true, true><<<grid, 256, GEMM_SMEM>>>(p);
    } else {
        if (outbf16) gemm_fused_kernel<false, true ><<<grid, 256, GEMM_SMEM>>>(p);
        else         gemm_fused_kernel<false, false><<<grid, 256, GEMM_SMEM>>>(p);
    }
}

static void run_scans(const int* cnt, int n, int* bsum, int* rowptr, int* nextp) {
    int nb = (n + SCB - 1) / SCB;
    scan1_kernel<<<nb, SCB>>>(cnt, n, bsum);
    scan2_kernel<<<1, SCB>>>(bsum, nb);
    scan3_kernel<<<nb, SCB>>>(cnt, n, bsum, rowptr, nextp);
}

static void run_gather(const __nv_bfloat16* feat, const int* rowptr, const int* csr_src,
                       int num_dst, __nv_bfloat16* agg) {
    gather_mean_kernel<<<(num_dst + 7) / 8, 256>>>(feat, rowptr, csr_src, num_dst, agg);
}

extern "C" void kernel_launch(void* const* d_in, const int* in_sizes, int n_in,
                              void* d_out, int out_size) {
    const float* x_paper          = (const float*)d_in[0];
    const float* emb_author       = (const float*)d_in[1];
    const float* lin_paper_w      = (const float*)d_in[2];
    const float* lin_paper_b      = (const float*)d_in[3];
    const float* c0_root_paper_w  = (const float*)d_in[4];
    const float* c0_root_paper_b  = (const float*)d_in[5];
    const float* c0_root_author_w = (const float*)d_in[6];
    const float* c0_root_author_b = (const float*)d_in[7];
    const float* c0_rel_writes_w  = (const float*)d_in[8];
    const float* c0_rel_cites_w   = (const float*)d_in[9];
    const float* c0_rel_revw_w    = (const float*)d_in[10];
    const float* c1_root_w        = (const float*)d_in[11];
    const float* c1_root_b        = (const float*)d_in[12];
    const float* c1_rel_writes_w  = (const float*)d_in[13];
    const float* c1_rel_cites_w   = (const float*)d_in[14];
    const int*   writes_src       = (const int*)d_in[15];
    const int*   writes_dst       = (const int*)d_in[16];
    const int*   cites_src        = (const int*)d_in[17];
    const int*   cites_dst        = (const int*)d_in[18];
    const int*   revw_src         = (const int*)d_in[19];
    const int*   revw_dst         = (const int*)d_in[20];

    const int E_W = in_sizes[15];
    const int E_C = in_sizes[17];
    float* out = (float*)d_out;

    __nv_bfloat16 *hp, *outp, *outa, *aggA, *aggB, *emba, *xb;
    __nv_bfloat16 *wlin, *w0rp, *w0ra, *w0w, *w0c, *w0r, *w1rt, *w1w, *w1c;
    int *cntW, *cntC, *cntR, *rpW, *rpC, *rpR, *nxW, *nxC, *nxR, *csW, *csC, *csR, *bsum;
    cudaGetSymbolAddress((void**)&hp,   g_hp);
    cudaGetSymbolAddress((void**)&outp, g_outp);
    cudaGetSymbolAddress((void**)&outa, g_outa);
    cudaGetSymbolAddress((void**)&aggA, g_aggA);
    cudaGetSymbolAddress((void**)&aggB, g_aggB);
    cudaGetSymbolAddress((void**)&emba, g_emba);
    cudaGetSymbolAddress((void**)&xb,   g_xb);
    cudaGetSymbolAddress((void**)&wlin, g_wlin);
    cudaGetSymbolAddress((void**)&w0rp, g_w0rp);
    cudaGetSymbolAddress((void**)&w0ra, g_w0ra);
    cudaGetSymbolAddress((void**)&w0w,  g_w0w);
    cudaGetSymbolAddress((void**)&w0c,  g_w0c);
    cudaGetSymbolAddress((void**)&w0r,  g_w0r);
    cudaGetSymbolAddress((void**)&w1rt, g_w1rt);
    cudaGetSymbolAddress((void**)&w1w,  g_w1w);
    cudaGetSymbolAddress((void**)&w1c,  g_w1c);
    cudaGetSymbolAddress((void**)&cntW, g_cntW);
    cudaGetSymbolAddress((void**)&cntC, g_cntC);
    cudaGetSymbolAddress((void**)&cntR, g_cntR);
    cudaGetSymbolAddress((void**)&rpW,  g_rpW);
    cudaGetSymbolAddress((void**)&rpC,  g_rpC);
    cudaGetSymbolAddress((void**)&rpR,  g_rpR);
    cudaGetSymbolAddress((void**)&nxW,  g_nxW);
    cudaGetSymbolAddress((void**)&nxC,  g_nxC);
    cudaGetSymbolAddress((void**)&nxR,  g_nxR);
    cudaGetSymbolAddress((void**)&csW,  g_csW);
    cudaGetSymbolAddress((void**)&csC,  g_csC);
    cudaGetSymbolAddress((void**)&csR,  g_csR);
    cudaGetSymbolAddress((void**)&bsum, g_bsum);

    cudaFuncSetAttribute(gemm_fused_kernel<false, true >, cudaFuncAttributeMaxDynamicSharedMemorySize, GEMM_SMEM);
    cudaFuncSetAttribute(gemm_fused_kernel<true,  true >, cudaFuncAttributeMaxDynamicSharedMemorySize, GEMM_SMEM);
    cudaFuncSetAttribute(gemm_fused_kernel<false, false>, cudaFuncAttributeMaxDynamicSharedMemorySize, GEMM_SMEM);

    // --- feature conversions ---
    f2b_kernel<<<((A_N * H_C / 4) + 255) / 256, 256>>>(
        (const float4*)emb_author, (uint2*)emba, A_N * H_C / 4);
    f2b_kernel<<<((P_N * IN_C / 4) + 255) / 256, 256>>>(
        (const float4*)x_paper, (uint2*)xb, P_N * IN_C / 4);

    // --- all weight conversions ---
    {
        W2B b = {};
        const float* srcs[9] = {lin_paper_w, c0_root_paper_w, c0_root_author_w,
                                c0_rel_writes_w, c0_rel_cites_w, c0_rel_revw_w,
                                c1_root_w, c1_rel_writes_w, c1_rel_cites_w};
        __nv_bfloat16* dsts[9] = {wlin, w0rp, w0ra, w0w, w0c, w0r, w1rt, w1w, w1c};
        int Ns[9]    = {H_C, H_C, H_C, H_C, H_C, H_C, OUT_C, OUT_C, OUT_C};
        int Npads[9] = {H_C, H_C, H_C, H_C, H_C, H_C, 352, 352, 352};
        int Ks[9]    = {IN_C, H_C, H_C, H_C, H_C, H_C, H_C, H_C, H_C};
        int cum = 0;
        for (int q = 0; q < 9; q++) {
            b.src[q] = srcs[q]; b.dst[q] = dsts[q];
            b.N[q] = Ns[q]; b.Npad[q] = Npads[q];
            b.cum[q] = cum; cum += Ks[q] * Npads[q];
        }
        b.cum[9] = cum;
        w2b_all_kernel<<<(cum + 255) / 256, 256>>>(b);
    }

    // --- CSR: counts ---
    {
        int na4 = P_N / 4, nb4 = P_N / 4, nc4 = A_N / 4;
        fill3_kernel<<<(na4 + nb4 + nc4 + 255) / 256, 256>>>(
            (int4*)cntW, na4, (int4*)cntC, nb4, (int4*)cntR, nc4);
    }
    count_int_kernel<<<(E_W + 255) / 256, 256>>>(writes_dst, E_W, cntW);

    // --- GEMM1 (hp = x@Wlin + b) ---
    {
        GemmParams p = {};
        p.A[0] = xb; p.B[0] = wlin; p.K[0] = IN_C;
        p.nseg = 1; p.bias = lin_paper_b; p.C = hp; p.M = P_N; p.N = H_C; p.Npad = H_C;
        run_gemm_fused(false, true, p);
    }

    // --- remaining CSR builds ---
    count_int_kernel<<<(E_C + 255) / 256, 256>>>(cites_dst, E_C, cntC);
    count_int_kernel<<<(E_W + 255) / 256, 256>>>(revw_dst,  E_W, cntR);
    run_scans(cntW, P_N, bsum, rpW, nxW);
    build_csr_kernel<<<(E_W + 255) / 256, 256>>>(writes_src, writes_dst, E_W, nxW, csW);
    run_scans(cntC, P_N, bsum, rpC, nxC);
    build_csr_kernel<<<(E_C + 255) / 256, 256>>>(cites_src, cites_dst, E_C, nxC, csC);
    run_scans(cntR, A_N, bsum, rpR, nxR);
    build_csr_kernel<<<(E_W + 255) / 256, 256>>>(revw_src, revw_dst, E_W, nxR, csR);

    // --- layer-0 gathers + paper GEMM ---
    run_gather(emba, rpW, csW, P_N, aggA);
    run_gather(hp,   rpC, csC, P_N, aggB);
    {
        GemmParams p = {};
        p.A[0] = hp;   p.B[0] = w0rp; p.K[0] = H_C;
        p.A[1] = aggA; p.B[1] = w0w;  p.K[1] = H_C;
        p.A[2] = aggB; p.B[2] = w0c;  p.K[2] = H_C;
        p.nseg = 3; p.bias = c0_root_paper_b; p.C = outp; p.M = P_N; p.N = H_C; p.Npad = H_C;
        run_gemm_fused(true, true, p);
    }

    // --- author side ---
    run_gather(hp, rpR, csR, A_N, aggA);
    {
        GemmParams p = {};
        p.A[0] = emba; p.B[0] = w0ra; p.K[0] = H_C;
        p.A[1] = aggA; p.B[1] = w0r;  p.K[1] = H_C;
        p.nseg = 2; p.bias = c0_root_author_b; p.C = outa; p.M = A_N; p.N = H_C; p.Npad = H_C;
        run_gemm_fused(true, true, p);
    }

    // --- layer-1 gathers + output GEMM ---
    run_gather(outa, rpW, csW, P_N, aggA);
    run_gather(outp, rpC, csC, P_N, aggB);
    {
        GemmParams p = {};
        p.A[0] = outp; p.B[0] = w1rt; p.K[0] = H_C;
        p.A[1] = aggA; p.B[1] = w1w;  p.K[1] = H_C;
        p.A[2] = aggB; p.B[2] = w1c;  p.K[2] = H_C;
        p.nseg = 3; p.bias = c1_root_b; p.C = out; p.M = P_N; p.N = OUT_C; p.Npad = 352;
        run_gemm_fused(false, false, p);
    }

    // --- log_softmax ---
    log_softmax_kernel<<<P_N, 128>>>(out, OUT_C);
}